// round 13
// baseline (speedup 1.0000x reference)
#include <cuda_runtime.h>
#include <cuda_bf16.h>
#include <cuda_fp16.h>
#include <cstdint>
#include <math.h>

#define CTXN   2048
#define DMODEL 2048
#define NH     16
#define HD     128
#define BSZ    2
#define MROWS  (BSZ * CTXN)   // 4096
#define NSM    148
#define PGRID  (2 * NSM)      // persistent grid: 2 CTAs/SM

// ---------------- scratch (device globals; no allocation allowed) ----------
__device__ __nv_bfloat16 g_xh[MROWS * DMODEL];     // x bf16 hi/lo (QK proj)
__device__ __nv_bfloat16 g_xl[MROWS * DMODEL];
__device__ __half        g_xfh[MROWS * DMODEL];    // x fp16 hi/lo (V proj)
__device__ __half        g_xfl[MROWS * DMODEL];
__device__ __nv_bfloat16 g_wqh[DMODEL * DMODEL], g_wql[DMODEL * DMODEL];
__device__ __nv_bfloat16 g_wkh[DMODEL * DMODEL], g_wkl[DMODEL * DMODEL];
__device__ __half        g_wvh[DMODEL * DMODEL];   // Wv fp16 single
__device__ __half        g_woh[DMODEL * DMODEL];   // Wo fp16 single
__device__ __nv_bfloat16 g_Qh[BSZ * NH * CTXN * HD], g_Ql[BSZ * NH * CTXN * HD];
__device__ __nv_bfloat16 g_Kh[BSZ * NH * CTXN * HD], g_Kl[BSZ * NH * CTXN * HD];
__device__ __half        g_Vh[BSZ * NH * CTXN * HD], g_Vl[BSZ * NH * CTXN * HD];
__device__ __half        g_ctxh[MROWS * DMODEL];   // ctx fp16 hi/lo
__device__ __half        g_ctxl[MROWS * DMODEL];
__device__ float2 g_rope[64 * CTXN];               // [d][s] (sin, cos)

// ======================= low-level helpers =================================
__device__ __forceinline__ uint32_t smem_to_u32(const void* p) {
    uint32_t a;
    asm("{ .reg .u64 t; cvta.to.shared.u64 t, %1; cvt.u32.u64 %0, t; }"
        : "=r"(a) : "l"(p));
    return a;
}
__device__ __forceinline__ void cpa16(uint32_t dst, const void* src) {
    asm volatile("cp.async.cg.shared.global [%0], [%1], 16;" :: "r"(dst), "l"(src));
}
#define CP_COMMIT() asm volatile("cp.async.commit_group;" ::: "memory")
#define CP_WAIT(n)  asm volatile("cp.async.wait_group %0;" :: "n"(n) : "memory")

__device__ __forceinline__ void ldsm4(uint32_t* r, uint32_t addr) {
    asm volatile("ldmatrix.sync.aligned.m8n8.x4.shared.b16 {%0,%1,%2,%3}, [%4];"
        : "=r"(r[0]), "=r"(r[1]), "=r"(r[2]), "=r"(r[3]) : "r"(addr));
}
__device__ __forceinline__ void ldsm4t(uint32_t* r, uint32_t addr) {
    asm volatile("ldmatrix.sync.aligned.m8n8.x4.trans.shared.b16 {%0,%1,%2,%3}, [%4];"
        : "=r"(r[0]), "=r"(r[1]), "=r"(r[2]), "=r"(r[3]) : "r"(addr));
}
__device__ __forceinline__ void mma_bf16(float* d, const uint32_t* a, const uint32_t* b) {
    asm volatile(
        "mma.sync.aligned.m16n8k16.row.col.f32.bf16.bf16.f32 "
        "{%0,%1,%2,%3}, {%4,%5,%6,%7}, {%8,%9}, {%0,%1,%2,%3};"
        : "+f"(d[0]), "+f"(d[1]), "+f"(d[2]), "+f"(d[3])
        : "r"(a[0]), "r"(a[1]), "r"(a[2]), "r"(a[3]), "r"(b[0]), "r"(b[1]));
}
__device__ __forceinline__ void mma_f16(float* d, const uint32_t* a, const uint32_t* b) {
    asm volatile(
        "mma.sync.aligned.m16n8k16.row.col.f32.f16.f16.f32 "
        "{%0,%1,%2,%3}, {%4,%5,%6,%7}, {%8,%9}, {%0,%1,%2,%3};"
        : "+f"(d[0]), "+f"(d[1]), "+f"(d[2]), "+f"(d[3])
        : "r"(a[0]), "r"(a[1]), "r"(a[2]), "r"(a[3]), "r"(b[0]), "r"(b[1]));
}
__device__ __forceinline__ uint32_t pack_h16(float a, float b) {
    __half2 p = __halves2half2(__float2half(a), __float2half(b));
    return *(uint32_t*)&p;
}

// ======================= prep kernels ======================================
__global__ void conv_x(const float* __restrict__ x) {
    size_t i = (size_t)blockIdx.x * 256 + threadIdx.x;   // over elems/4
    float4 v = ((const float4*)x)[i];
    float vv[4] = {v.x, v.y, v.z, v.w};
#pragma unroll
    for (int p = 0; p < 2; p++) {
        float a = vv[2 * p], b = vv[2 * p + 1];
        __nv_bfloat16 bh0 = __float2bfloat16(a), bh1 = __float2bfloat16(b);
        ((__nv_bfloat162*)g_xh)[2 * i + p] = __halves2bfloat162(bh0, bh1);
        ((__nv_bfloat162*)g_xl)[2 * i + p] = __halves2bfloat162(
            __float2bfloat16(a - __bfloat162float(bh0)),
            __float2bfloat16(b - __bfloat162float(bh1)));
        __half fh0 = __float2half(a), fh1 = __float2half(b);
        ((__half2*)g_xfh)[2 * i + p] = __halves2half2(fh0, fh1);
        ((__half2*)g_xfl)[2 * i + p] = __halves2half2(
            __float2half(a - __half2float(fh0)),
            __float2half(b - __half2float(fh1)));
    }
}

// transpose + convert: out[n][k] = W[k][n].  z 0/1: bf16 hi/lo; z 2/3: fp16 single.
__global__ void conv_w(const float* __restrict__ Wq, const float* __restrict__ Wk,
                       const float* __restrict__ Wv, const float* __restrict__ Wo) {
    __shared__ float t[32][33];
    int z = blockIdx.z;
    const float* W = (z == 0) ? Wq : (z == 1) ? Wk : (z == 2) ? Wv : Wo;
    int bx = blockIdx.x * 32, by = blockIdx.y * 32;     // bx: n, by: k
    int tx = threadIdx.x, ty = threadIdx.y;
#pragma unroll
    for (int i = 0; i < 4; i++)
        t[ty + i * 8][tx] = W[(size_t)(by + ty + i * 8) * DMODEL + bx + tx];
    __syncthreads();
#pragma unroll
    for (int i = 0; i < 4; i++) {
        float v = t[tx][ty + i * 8];
        size_t oi = (size_t)(bx + ty + i * 8) * DMODEL + by + tx;
        if (z < 2) {
            __nv_bfloat16 h = __float2bfloat16(v);
            __nv_bfloat16 l = __float2bfloat16(v - __bfloat162float(h));
            if (z == 0) { g_wqh[oi] = h; g_wql[oi] = l; }
            else        { g_wkh[oi] = h; g_wkl[oi] = l; }
        } else {
            __half h = __float2half(v);
            if (z == 2) g_wvh[oi] = h;
            else        g_woh[oi] = h;
        }
    }
}

__global__ void rope_table() {
    int d = blockIdx.x;                                  // 0..63
    double invf = pow(10000.0, -(double)d / 64.0);
    const double TWO_PI = 6.283185307179586476925286766559;
    for (int s = threadIdx.x; s < CTXN; s += blockDim.x) {
        double a = (double)s * invf;
        double r = a - TWO_PI * floor(a / TWO_PI);
        float sn, cs;
        sincosf((float)r, &sn, &cs);
        g_rope[d * CTXN + s] = make_float2(sn, cs);
    }
}

// ======================= bf16 3-term GEMM core =============================
#define KC 32
#define SROW 40
#define MAT_BYTES (128 * SROW * 2)            // 10240
#define STAGE_BYTES (4 * MAT_BYTES)           // 40960
#define GEMM_SMEM (2 * STAGE_BYTES)           // 81920
#define NCHUNK (DMODEL / KC)                  // 64

__device__ __forceinline__ void load_stage(
    uint32_t sb, int kt,
    const __nv_bfloat16* __restrict__ Ah, const __nv_bfloat16* __restrict__ Al,
    const __nv_bfloat16* __restrict__ Bh, const __nv_bfloat16* __restrict__ Bl,
    int mBase, int nBase, int tid)
{
#pragma unroll
    for (int i = 0; i < 2; i++) {
        int fid = tid + i * 256;
        int row = fid >> 2, u = fid & 3;
        uint32_t off = (uint32_t)(row * (SROW * 2) + u * 16);
        size_t ga = (size_t)(mBase + row) * DMODEL + kt + u * 8;
        size_t gb = (size_t)(nBase + row) * DMODEL + kt + u * 8;
        cpa16(sb + off,                 &Ah[ga]);
        cpa16(sb + MAT_BYTES + off,     &Al[ga]);
        cpa16(sb + 2 * MAT_BYTES + off, &Bh[gb]);
        cpa16(sb + 3 * MAT_BYTES + off, &Bl[gb]);
    }
}

__device__ __forceinline__ void compute_stage(
    uint32_t sb, int wm, int wn2, int lane, float (&acc)[4][4][4])
{
    uint32_t Ab  = sb;
    uint32_t Alb = sb + MAT_BYTES;
    uint32_t Bb  = sb + 2 * MAT_BYTES;
    uint32_t Blb = sb + 3 * MAT_BYTES;
#pragma unroll
    for (int ks = 0; ks < KC / 16; ks++) {
        uint32_t ah[4][4], al[4][4];
#pragma unroll
        for (int i = 0; i < 4; i++) {
            uint32_t aoff = (uint32_t)(((wm + i * 16 + (lane & 15)) * SROW
                             + (lane >> 4) * 8 + ks * 16) * 2);
            ldsm4(ah[i], Ab + aoff);
            ldsm4(al[i], Alb + aoff);
        }
        uint32_t bh[2][4], bl[2][4];
#pragma unroll
        for (int jp = 0; jp < 2; jp++) {
            int bn = wn2 + jp * 64 + (lane & 7) + ((lane >> 4) & 1) * 8;
            int bk = ((lane >> 3) & 1) * 8 + ks * 16;
            uint32_t boff = (uint32_t)((bn * SROW + bk) * 2);
            ldsm4(bh[jp], Bb + boff);
            ldsm4(bl[jp], Blb + boff);
        }
#pragma unroll
        for (int i = 0; i < 4; i++) {
#pragma unroll
            for (int jp = 0; jp < 2; jp++) {
                mma_bf16(acc[i][jp * 2],     ah[i], &bh[jp][0]);
                mma_bf16(acc[i][jp * 2 + 1], ah[i], &bh[jp][2]);
                mma_bf16(acc[i][jp * 2],     ah[i], &bl[jp][0]);
                mma_bf16(acc[i][jp * 2 + 1], ah[i], &bl[jp][2]);
                mma_bf16(acc[i][jp * 2],     al[i], &bh[jp][0]);
                mma_bf16(acc[i][jp * 2 + 1], al[i], &bh[jp][2]);
            }
        }
    }
}

__device__ __forceinline__ void gemm_mainloop(
    const __nv_bfloat16* __restrict__ Ah, const __nv_bfloat16* __restrict__ Al,
    const __nv_bfloat16* __restrict__ Bh, const __nv_bfloat16* __restrict__ Bl,
    int mBase, int nBase, uint32_t smem_u, float (&acc)[4][4][4])
{
    const int tid = threadIdx.x;
    const int lane = tid & 31, wid = tid >> 5;
    const int wm = (wid >> 2) * 64, wn2 = (wid & 3) * 16;

#pragma unroll
    for (int i = 0; i < 4; i++)
#pragma unroll
        for (int j = 0; j < 4; j++)
#pragma unroll
            for (int r = 0; r < 4; r++) acc[i][j][r] = 0.f;

    __syncthreads();   // protect buf0 from lagging readers of previous tile
    load_stage(smem_u, 0, Ah, Al, Bh, Bl, mBase, nBase, tid);
    CP_COMMIT();

    for (int c = 0; c < NCHUNK; c++) {
        CP_WAIT(0);
        __syncthreads();
        if (c + 1 < NCHUNK) {
            load_stage(smem_u + (uint32_t)((c + 1) & 1) * STAGE_BYTES,
                       (c + 1) * KC, Ah, Al, Bh, Bl, mBase, nBase, tid);
            CP_COMMIT();
        }
        compute_stage(smem_u + (uint32_t)(c & 1) * STAGE_BYTES, wm, wn2, lane, acc);
    }
}

// ======================= fp16 2-term GEMM core =============================
#define STAGE_H (3 * MAT_BYTES)               // 30720
#define GEMM_H_SMEM (2 * STAGE_H)             // 61440

__device__ __forceinline__ void load_stage_h(
    uint32_t sb, int kt,
    const __half* __restrict__ Ah, const __half* __restrict__ Al,
    const __half* __restrict__ Bh,
    int mBase, int nBase, int tid)
{
#pragma unroll
    for (int i = 0; i < 2; i++) {
        int fid = tid + i * 256;
        int row = fid >> 2, u = fid & 3;
        uint32_t off = (uint32_t)(row * (SROW * 2) + u * 16);
        size_t ga = (size_t)(mBase + row) * DMODEL + kt + u * 8;
        size_t gb = (size_t)(nBase + row) * DMODEL + kt + u * 8;
        cpa16(sb + off,                 &Ah[ga]);
        cpa16(sb + MAT_BYTES + off,     &Al[ga]);
        cpa16(sb + 2 * MAT_BYTES + off, &Bh[gb]);
    }
}

__device__ __forceinline__ void compute_stage_h(
    uint32_t sb, int wm, int wn2, int lane, float (&acc)[4][4][4])
{
    uint32_t Ab  = sb;
    uint32_t Alb = sb + MAT_BYTES;
    uint32_t Bb  = sb + 2 * MAT_BYTES;
#pragma unroll
    for (int ks = 0; ks < KC / 16; ks++) {
        uint32_t ah[4][4], al[4][4];
#pragma unroll
        for (int i = 0; i < 4; i++) {
            uint32_t aoff = (uint32_t)(((wm + i * 16 + (lane & 15)) * SROW
                             + (lane >> 4) * 8 + ks * 16) * 2);
            ldsm4(ah[i], Ab + aoff);
            ldsm4(al[i], Alb + aoff);
        }
        uint32_t bh[2][4];
#pragma unroll
        for (int jp = 0; jp < 2; jp++) {
            int bn = wn2 + jp * 64 + (lane & 7) + ((lane >> 4) & 1) * 8;
            int bk = ((lane >> 3) & 1) * 8 + ks * 16;
            uint32_t boff = (uint32_t)((bn * SROW + bk) * 2);
            ldsm4(bh[jp], Bb + boff);
        }
#pragma unroll
        for (int i = 0; i < 4; i++) {
#pragma unroll
            for (int jp = 0; jp < 2; jp++) {
                mma_f16(acc[i][jp * 2],     ah[i], &bh[jp][0]);
                mma_f16(acc[i][jp * 2 + 1], ah[i], &bh[jp][2]);
                mma_f16(acc[i][jp * 2],     al[i], &bh[jp][0]);
                mma_f16(acc[i][jp * 2 + 1], al[i], &bh[jp][2]);
            }
        }
    }
}

__device__ __forceinline__ void gemm_mainloop_h(
    const __half* __restrict__ Ah, const __half* __restrict__ Al,
    const __half* __restrict__ Bh,
    int mBase, int nBase, uint32_t smem_u, float (&acc)[4][4][4])
{
    const int tid = threadIdx.x;
    const int lane = tid & 31, wid = tid >> 5;
    const int wm = (wid >> 2) * 64, wn2 = (wid & 3) * 16;

#pragma unroll
    for (int i = 0; i < 4; i++)
#pragma unroll
        for (int j = 0; j < 4; j++)
#pragma unroll
            for (int r = 0; r < 4; r++) acc[i][j][r] = 0.f;

    __syncthreads();
    load_stage_h(smem_u, 0, Ah, Al, Bh, mBase, nBase, tid);
    CP_COMMIT();

    for (int c = 0; c < NCHUNK; c++) {
        CP_WAIT(0);
        __syncthreads();
        if (c + 1 < NCHUNK) {
            load_stage_h(smem_u + (uint32_t)((c + 1) & 1) * STAGE_H,
                         (c + 1) * KC, Ah, Al, Bh, mBase, nBase, tid);
            CP_COMMIT();
        }
        compute_stage_h(smem_u + (uint32_t)(c & 1) * STAGE_H, wm, wn2, lane, acc);
    }
}

// ======================= QK GEMM (persistent, + fused RoPE) ================
#define QK_TILES (16 * 32 * 2)                // nx * my * z = 1024
__global__ void __launch_bounds__(256, 2) qk_tc() {
    extern __shared__ char smem[];
    uint32_t smem_u = smem_to_u32(smem);
    const int tid = threadIdx.x;
    const int lane = tid & 31, wid = tid >> 5;
    const int wm = (wid >> 2) * 64, wn2 = (wid & 3) * 16;

    for (int t = blockIdx.x; t < QK_TILES; t += PGRID) {
        const int nx = t & 15;
        const int my = (t >> 4) & 31;
        const int z  = t >> 9;                   // 0=Q, 1=K
        const __nv_bfloat16* Bh_ = (z == 0) ? g_wqh : g_wkh;
        const __nv_bfloat16* Bl_ = (z == 0) ? g_wql : g_wkl;
        __nv_bfloat16* Dh = (z == 0) ? g_Qh : g_Kh;
        __nv_bfloat16* Dl = (z == 0) ? g_Ql : g_Kl;
        const int mBase = my * 128, nBase = nx * 128;
        const int head = nx;

        float acc[4][4][4];
        gemm_mainloop(g_xh, g_xl, Bh_, Bl_, mBase, nBase, smem_u, acc);

#pragma unroll
        for (int i = 0; i < 4; i++) {
            int gm0 = mBase + wm + i * 16 + (lane >> 2);
#pragma unroll
            for (int rr = 0; rr < 2; rr++) {
                int gm = gm0 + rr * 8;
                int b = gm >> 11, s = gm & (CTXN - 1);
                size_t base = (((size_t)b * NH + head) * CTXN + s) * HD;
#pragma unroll
                for (int jl = 0; jl < 2; jl++) {
                    int c = wn2 + jl * 8 + (lane & 3) * 2;
                    float lo0 = acc[i][jl][rr * 2 + 0];
                    float lo1 = acc[i][jl][rr * 2 + 1];
                    float hi0 = acc[i][jl + 2][rr * 2 + 0];
                    float hi1 = acc[i][jl + 2][rr * 2 + 1];
                    float2 sc0 = g_rope[c * CTXN + s];
                    float2 sc1 = g_rope[(c + 1) * CTXN + s];
                    float t0 = lo0 * sc0.y - hi0 * sc0.x;
                    float t2 = hi0 * sc0.y + lo0 * sc0.x;
                    float t1 = lo1 * sc1.y - hi1 * sc1.x;
                    float t3 = hi1 * sc1.y + lo1 * sc1.x;
                    lo0 = t0; lo1 = t1; hi0 = t2; hi1 = t3;
                    __nv_bfloat16 a0 = __float2bfloat16(lo0), a1 = __float2bfloat16(lo1);
                    __nv_bfloat16 b0 = __float2bfloat16(hi0), b1 = __float2bfloat16(hi1);
                    *(__nv_bfloat162*)&Dh[base + c]      = __halves2bfloat162(a0, a1);
                    *(__nv_bfloat162*)&Dh[base + c + 64] = __halves2bfloat162(b0, b1);
                    *(__nv_bfloat162*)&Dl[base + c]      = __halves2bfloat162(
                        __float2bfloat16(lo0 - __bfloat162float(a0)),
                        __float2bfloat16(lo1 - __bfloat162float(a1)));
                    *(__nv_bfloat162*)&Dl[base + c + 64] = __halves2bfloat162(
                        __float2bfloat16(hi0 - __bfloat162float(b0)),
                        __float2bfloat16(hi1 - __bfloat162float(b1)));
                }
            }
        }
    }
}

// ======================= V GEMM (persistent, fp16 2-term) ==================
#define V_TILES (16 * 32)                      // 512
__global__ void __launch_bounds__(256, 2) v_tc() {
    extern __shared__ char smem[];
    uint32_t smem_u = smem_to_u32(smem);
    const int tid = threadIdx.x;
    const int lane = tid & 31, wid = tid >> 5;
    const int wm = (wid >> 2) * 64, wn2 = (wid & 3) * 16;

    for (int t = blockIdx.x; t < V_TILES; t += PGRID) {
        const int nx = t & 15;
        const int my = t >> 4;
        const int mBase = my * 128, nBase = nx * 128;
        const int head = nx;

        float acc[4][4][4];
        gemm_mainloop_h(g_xfh, g_xfl, g_wvh, mBase, nBase, smem_u, acc);

#pragma unroll
        for (int i = 0; i < 4; i++) {
            int gm0 = mBase + wm + i * 16 + (lane >> 2);
#pragma unroll
            for (int rr = 0; rr < 2; rr++) {
                int gm = gm0 + rr * 8;
                int b = gm >> 11, s = gm & (CTXN - 1);
                size_t base = (((size_t)b * NH + head) * CTXN + s) * HD;
#pragma unroll
                for (int jl = 0; jl < 2; jl++) {
                    int c = wn2 + jl * 8 + (lane & 3) * 2;
                    float lo0 = acc[i][jl][rr * 2 + 0];
                    float lo1 = acc[i][jl][rr * 2 + 1];
                    float hi0 = acc[i][jl + 2][rr * 2 + 0];
                    float hi1 = acc[i][jl + 2][rr * 2 + 1];
                    __half a0 = __float2half(lo0), a1 = __float2half(lo1);
                    __half b0 = __float2half(hi0), b1 = __float2half(hi1);
                    *(__half2*)&g_Vh[base + c]      = __halves2half2(a0, a1);
                    *(__half2*)&g_Vh[base + c + 64] = __halves2half2(b0, b1);
                    *(__half2*)&g_Vl[base + c]      = __halves2half2(
                        __float2half(lo0 - __half2float(a0)),
                        __float2half(lo1 - __half2float(a1)));
                    *(__half2*)&g_Vl[base + c + 64] = __halves2half2(
                        __float2half(hi0 - __half2float(b0)),
                        __float2half(hi1 - __half2float(b1)));
                }
            }
        }
    }
}

// ======================= output projection (persistent, fp16 2-term) =======
__global__ void __launch_bounds__(256, 2) out_tc(float* __restrict__ out) {
    extern __shared__ char smem[];
    uint32_t smem_u = smem_to_u32(smem);
    const int tid = threadIdx.x;
    const int lane = tid & 31, wid = tid >> 5;
    const int wm = (wid >> 2) * 64, wn2 = (wid & 3) * 16;

    for (int t = blockIdx.x; t < V_TILES; t += PGRID) {
        const int nx = t & 15;
        const int my = t >> 4;
        const int mBase = my * 128, nBase = nx * 128;

        float acc[4][4][4];
        gemm_mainloop_h(g_ctxh, g_ctxl, g_woh, mBase, nBase, smem_u, acc);

#pragma unroll
        for (int i = 0; i < 4; i++) {
            int gm0 = mBase + wm + i * 16 + (lane >> 2);
#pragma unroll
            for (int rr = 0; rr < 2; rr++) {
                int gm = gm0 + rr * 8;
                size_t rb = (size_t)gm * DMODEL + nBase;
#pragma unroll
                for (int jl = 0; jl < 2; jl++) {
                    int c = wn2 + jl * 8 + (lane & 3) * 2;
                    *(float2*)&out[rb + c] =
                        make_float2(acc[i][jl][rr * 2], acc[i][jl][rr * 2 + 1]);
                    *(float2*)&out[rb + c + 64] =
                        make_float2(acc[i][jl + 2][rr * 2], acc[i][jl + 2][rr * 2 + 1]);
                }
            }
        }
    }
}

// ======================= tensor-core flash attention =======================
#define SA 136
#define AQH 0
#define AQL (128 * SA * 2)
#define ASTAGE0 (2 * 128 * SA * 2)               // 69632
#define ASTG (4 * 64 * SA * 2)                   // 69632 per stage
#define AKH 0
#define AKL (64 * SA * 2)
#define AVH (2 * 64 * SA * 2)
#define AVL (3 * 64 * SA * 2)
#define ATTN2_SMEM (ASTAGE0 + 2 * ASTG)          // 208896

__device__ __forceinline__ void load_kv_tile(uint32_t dst, size_t bhoff,
                                             int kvrow, int tid) {
#pragma unroll
    for (int i = 0; i < 4; i++) {
        int cid = tid + i * 256;
        int row = cid >> 4, u = cid & 15;
        uint32_t off = (uint32_t)(row * (SA * 2) + u * 16);
        size_t g = bhoff + (size_t)(kvrow + row) * HD + u * 8;
        cpa16(dst + AKH + off, &g_Kh[g]);
        cpa16(dst + AKL + off, &g_Kl[g]);
        cpa16(dst + AVH + off, &g_Vh[g]);
        cpa16(dst + AVL + off, &g_Vl[g]);
    }
}

__global__ void __launch_bounds__(256, 1) attn_tc() {
    extern __shared__ char smc[];
    uint32_t su = smem_to_u32(smc);
    const int tid = threadIdx.x, lane = tid & 31, wid = tid >> 5;
    const int qt = 15 - (int)blockIdx.x;
    const int bh = blockIdx.y;
    const int b = bh >> 4, h = bh & 15;
    const size_t bhoff = (size_t)bh * CTXN * HD;
    const int qbase = qt * 128;
    const int wm = wid * 16;
    const int ntiles = 2 * qt + 2;

#pragma unroll
    for (int i = 0; i < 8; i++) {
        int cid = tid + i * 256;
        int row = cid >> 4, u = cid & 15;
        uint32_t off = (uint32_t)(row * (SA * 2) + u * 16);
        size_t g = bhoff + (size_t)(qbase + row) * HD + u * 8;
        cpa16(su + AQH + off, &g_Qh[g]);
        cpa16(su + AQL + off, &g_Ql[g]);
    }
    load_kv_tile(su + ASTAGE0, bhoff, 0, tid);
    CP_COMMIT();

    float oacc[16][4];
#pragma unroll
    for (int i = 0; i < 16; i++)
#pragma unroll
        for (int r = 0; r < 4; r++) oacc[i][r] = 0.f;
    float m0 = -INFINITY, m1 = -INFINITY, l0 = 0.f, l1 = 0.f;

    for (int j = 0; j < ntiles; j++) {
        int buf = j & 1;
        CP_WAIT(0);
        __syncthreads();
        if (j + 1 < ntiles) {
            load_kv_tile(su + ASTAGE0 + (uint32_t)(buf ^ 1) * ASTG,
                         bhoff, (j + 1) * 64, tid);
            CP_COMMIT();
        }
        const int kvbase = j * 64;
        if (kvbase <= qbase + wm + 15) {
            uint32_t kbh = su + ASTAGE0 + (uint32_t)buf * ASTG + AKH;
            uint32_t kbl = kbh + (AKL - AKH);
            uint32_t vbh = su + ASTAGE0 + (uint32_t)buf * ASTG + AVH;
            uint32_t vbl = vbh + (AVL - AVH);

            float sacc[8][4];
#pragma unroll
            for (int i = 0; i < 8; i++)
#pragma unroll
                for (int r = 0; r < 4; r++) sacc[i][r] = 0.f;
#pragma unroll
            for (int ks = 0; ks < 8; ks++) {
                uint32_t ah[4], al[4];
                uint32_t aoff = (uint32_t)(((wm + (lane & 15)) * SA
                                 + (lane >> 4) * 8 + ks * 16) * 2);
                ldsm4(ah, su + AQH + aoff);
                ldsm4(al, su + AQL + aoff);
#pragma unroll
                for (int jp = 0; jp < 4; jp++) {
                    int bn = jp * 16 + (lane & 7) + ((lane >> 4) & 1) * 8;
                    int bk = ((lane >> 3) & 1) * 8 + ks * 16;
                    uint32_t boff = (uint32_t)((bn * SA + bk) * 2);
                    uint32_t kh4[4], kl4[4];
                    ldsm4(kh4, kbh + boff);
                    ldsm4(kl4, kbl + boff);
                    mma_bf16(sacc[jp * 2],     ah, &kh4[0]);
                    mma_bf16(sacc[jp * 2 + 1], ah, &kh4[2]);
                    mma_bf16(sacc[jp * 2],     ah, &kl4[0]);
                    mma_bf16(sacc[jp * 2 + 1], ah, &kl4[2]);
                    mma_bf16(sacc[jp * 2],     al, &kh4[0]);
                    mma_bf16(sacc[jp * 2 + 1], al, &kh4[2]);
                }
            }

            if (kvbase + 63 > qbase + wm) {
                int row0 = qbase + wm + (lane >> 2);
                int c0 = kvbase + (lane & 3) * 2;
#pragma unroll
                for (int nb = 0; nb < 8; nb++) {
                    int c = c0 + nb * 8;
                    if (c     > row0)     sacc[nb][0] = -1e30f;
                    if (c + 1 > row0)     sacc[nb][1] = -1e30f;
                    if (c     > row0 + 8) sacc[nb][2] = -1e30f;
                    if (c + 1 > row0 + 8) sacc[nb][3] = -1e30f;
                }
            }

            float mx0 = -INFINITY, mx1 = -INFINITY;
#pragma unroll
            for (int nb = 0; nb < 8; nb++) {
                mx0 = fmaxf(mx0, fmaxf(sacc[nb][0], sacc[nb][1]));
                mx1 = fmaxf(mx1, fmaxf(sacc[nb][2], sacc[nb][3]));
            }
            mx0 = fmaxf(mx0, __shfl_xor_sync(0xffffffffu, mx0, 1));
            mx0 = fmaxf(mx0, __shfl_xor_sync(0xffffffffu, mx0, 2));
            mx1 = fmaxf(mx1, __shfl_xor_sync(0xffffffffu, mx1, 1));
            mx1 = fmaxf(mx1, __shfl_xor_sync(0xffffffffu, mx1, 2));
            float mn0 = fmaxf(m0, mx0), mn1 = fmaxf(m1, mx1);
            float a0 = __expf(m0 - mn0), a1 = __expf(m1 - mn1);
            m0 = mn0; m1 = mn1;
            float s0 = 0.f, s1 = 0.f;
#pragma unroll
            for (int nb = 0; nb < 8; nb++) {
                float p0 = __expf(sacc[nb][0] - mn0);
                float p1 = __expf(sacc[nb][1] - mn0);
                float p2 = __expf(sacc[nb][2] - mn1);
                float p3 = __expf(sacc[nb][3] - mn1);
                sacc[nb][0] = p0; sacc[nb][1] = p1;
                sacc[nb][2] = p2; sacc[nb][3] = p3;
                s0 += p0 + p1; s1 += p2 + p3;
            }
            s0 += __shfl_xor_sync(0xffffffffu, s0, 1);
            s0 += __shfl_xor_sync(0xffffffffu, s0, 2);
            s1 += __shfl_xor_sync(0xffffffffu, s1, 1);
            s1 += __shfl_xor_sync(0xffffffffu, s1, 2);
            l0 = l0 * a0 + s0;
            l1 = l1 * a1 + s1;
#pragma unroll
            for (int i = 0; i < 16; i++) {
                oacc[i][0] *= a0; oacc[i][1] *= a0;
                oacc[i][2] *= a1; oacc[i][3] *= a1;
            }

#pragma unroll
            for (int kb = 0; kb < 4; kb++) {
                uint32_t ph[4];
                ph[0] = pack_h16(sacc[2 * kb][0],     sacc[2 * kb][1]);
                ph[1] = pack_h16(sacc[2 * kb][2],     sacc[2 * kb][3]);
                ph[2] = pack_h16(sacc[2 * kb + 1][0], sacc[2 * kb + 1][1]);
                ph[3] = pack_h16(sacc[2 * kb + 1][2], sacc[2 * kb + 1][3]);
#pragma unroll
                for (int jn = 0; jn < 8; jn++) {
                    uint32_t voff = (uint32_t)(((kb * 16 + (lane & 15)) * SA
                                     + jn * 16 + (lane >> 4) * 8) * 2);
                    uint32_t vh4[4], vl4[4];
                    ldsm4t(vh4, vbh + voff);
                    ldsm4t(vl4, vbl + voff);
                    mma_f16(oacc[jn * 2],     ph, &vh4[0]);
                    mma_f16(oacc[jn * 2 + 1], ph, &vh4[2]);
                    mma_f16(oacc[jn * 2],     ph, &vl4[0]);
                    mma_f16(oacc[jn * 2 + 1], ph, &vl4[2]);
                }
            }
        }
    }

    float inv0 = 1.0f / l0, inv1 = 1.0f / l1;
    int sr0 = qbase + wm + (lane >> 2);
    size_t r0i = ((size_t)(b * CTXN + sr0)) * DMODEL + h * HD;
    size_t r1i = r0i + (size_t)8 * DMODEL;
#pragma unroll
    for (int jn = 0; jn < 16; jn++) {
        int c = jn * 8 + (lane & 3) * 2;
        float v0 = oacc[jn][0] * inv0, v1 = oacc[jn][1] * inv0;
        float v2 = oacc[jn][2] * inv1, v3 = oacc[jn][3] * inv1;
        __half h0a = __float2half(v0), h0b = __float2half(v1);
        __half h1a = __float2half(v2), h1b = __float2half(v3);
        *(__half2*)&g_ctxh[r0i + c] = __halves2half2(h0a, h0b);
        *(__half2*)&g_ctxh[r1i + c] = __halves2half2(h1a, h1b);
        *(__half2*)&g_ctxl[r0i + c] = __halves2half2(
            __float2half(v0 - __half2float(h0a)),
            __float2half(v1 - __half2float(h0b)));
        *(__half2*)&g_ctxl[r1i + c] = __halves2half2(
            __float2half(v2 - __half2float(h1a)),
            __float2half(v3 - __half2float(h1b)));
    }
}

// ======================= launch ============================================
extern "C" void kernel_launch(void* const* d_in, const int* in_sizes, int n_in,
                              void* d_out, int out_size)
{
    (void)in_sizes; (void)n_in; (void)out_size;
    const float* x  = (const float*)d_in[0];
    const float* Wq = (const float*)d_in[1];
    const float* Wk = (const float*)d_in[2];
    const float* Wv = (const float*)d_in[3];
    const float* Wo = (const float*)d_in[4];
    float* out = (float*)d_out;

    cudaFuncSetAttribute(qk_tc,   cudaFuncAttributeMaxDynamicSharedMemorySize, GEMM_SMEM);
    cudaFuncSetAttribute(v_tc,    cudaFuncAttributeMaxDynamicSharedMemorySize, GEMM_H_SMEM);
    cudaFuncSetAttribute(out_tc,  cudaFuncAttributeMaxDynamicSharedMemorySize, GEMM_H_SMEM);
    cudaFuncSetAttribute(attn_tc, cudaFuncAttributeMaxDynamicSharedMemorySize, ATTN2_SMEM);

    conv_x<<<(MROWS * DMODEL / 4) / 256, 256>>>(x);
    conv_w<<<dim3(64, 64, 4), dim3(32, 8)>>>(Wq, Wk, Wv, Wo);
    rope_table<<<64, 256>>>();
    qk_tc<<<PGRID, 256, GEMM_SMEM>>>();
    v_tc<<<PGRID, 256, GEMM_H_SMEM>>>();
    attn_tc<<<dim3(16, 32), 256, ATTN2_SMEM>>>();
    out_tc<<<PGRID, 256, GEMM_H_SMEM>>>(out);
}

// round 15
// speedup vs baseline: 1.0802x; 1.0802x over previous
#include <cuda_runtime.h>
#include <cuda_bf16.h>
#include <cuda_fp16.h>
#include <cstdint>
#include <math.h>

#define CTXN   2048
#define DMODEL 2048
#define NH     16
#define HD     128
#define BSZ    2
#define MROWS  (BSZ * CTXN)   // 4096

// ---------------- scratch (device globals; no allocation allowed) ----------
__device__ __nv_bfloat16 g_xh[MROWS * DMODEL];     // x bf16 hi/lo (QK proj)
__device__ __nv_bfloat16 g_xl[MROWS * DMODEL];
__device__ __half        g_xfh[MROWS * DMODEL];    // x fp16 hi/lo (V proj)
__device__ __half        g_xfl[MROWS * DMODEL];
__device__ __nv_bfloat16 g_wqh[DMODEL * DMODEL], g_wql[DMODEL * DMODEL];
__device__ __nv_bfloat16 g_wkh[DMODEL * DMODEL], g_wkl[DMODEL * DMODEL];
__device__ __half        g_wvh[DMODEL * DMODEL];   // Wv fp16 single
__device__ __half        g_woh[DMODEL * DMODEL];   // Wo fp16 single
__device__ __nv_bfloat16 g_Qh[BSZ * NH * CTXN * HD], g_Ql[BSZ * NH * CTXN * HD];
__device__ __nv_bfloat16 g_Kh[BSZ * NH * CTXN * HD], g_Kl[BSZ * NH * CTXN * HD];
__device__ __half        g_Vh[BSZ * NH * CTXN * HD], g_Vl[BSZ * NH * CTXN * HD];
__device__ __half        g_ctxh[MROWS * DMODEL];   // ctx fp16 hi/lo
__device__ __half        g_ctxl[MROWS * DMODEL];
__device__ float2 g_rope[64 * CTXN];               // [d][s] (sin, cos)

// ======================= low-level helpers =================================
__device__ __forceinline__ uint32_t smem_to_u32(const void* p) {
    uint32_t a;
    asm("{ .reg .u64 t; cvta.to.shared.u64 t, %1; cvt.u32.u64 %0, t; }"
        : "=r"(a) : "l"(p));
    return a;
}
__device__ __forceinline__ void cpa16(uint32_t dst, const void* src) {
    asm volatile("cp.async.cg.shared.global [%0], [%1], 16;" :: "r"(dst), "l"(src));
}
#define CP_COMMIT() asm volatile("cp.async.commit_group;" ::: "memory")
#define CP_WAIT(n)  asm volatile("cp.async.wait_group %0;" :: "n"(n) : "memory")

__device__ __forceinline__ void ldsm4(uint32_t* r, uint32_t addr) {
    asm volatile("ldmatrix.sync.aligned.m8n8.x4.shared.b16 {%0,%1,%2,%3}, [%4];"
        : "=r"(r[0]), "=r"(r[1]), "=r"(r[2]), "=r"(r[3]) : "r"(addr));
}
__device__ __forceinline__ void ldsm4t(uint32_t* r, uint32_t addr) {
    asm volatile("ldmatrix.sync.aligned.m8n8.x4.trans.shared.b16 {%0,%1,%2,%3}, [%4];"
        : "=r"(r[0]), "=r"(r[1]), "=r"(r[2]), "=r"(r[3]) : "r"(addr));
}
__device__ __forceinline__ void mma_bf16(float* d, const uint32_t* a, const uint32_t* b) {
    asm volatile(
        "mma.sync.aligned.m16n8k16.row.col.f32.bf16.bf16.f32 "
        "{%0,%1,%2,%3}, {%4,%5,%6,%7}, {%8,%9}, {%0,%1,%2,%3};"
        : "+f"(d[0]), "+f"(d[1]), "+f"(d[2]), "+f"(d[3])
        : "r"(a[0]), "r"(a[1]), "r"(a[2]), "r"(a[3]), "r"(b[0]), "r"(b[1]));
}
__device__ __forceinline__ void mma_f16(float* d, const uint32_t* a, const uint32_t* b) {
    asm volatile(
        "mma.sync.aligned.m16n8k16.row.col.f32.f16.f16.f32 "
        "{%0,%1,%2,%3}, {%4,%5,%6,%7}, {%8,%9}, {%0,%1,%2,%3};"
        : "+f"(d[0]), "+f"(d[1]), "+f"(d[2]), "+f"(d[3])
        : "r"(a[0]), "r"(a[1]), "r"(a[2]), "r"(a[3]), "r"(b[0]), "r"(b[1]));
}
__device__ __forceinline__ uint32_t pack_h16(float a, float b) {
    __half2 p = __halves2half2(__float2half(a), __float2half(b));
    return *(uint32_t*)&p;
}

// ======================= prep kernels ======================================
__global__ void conv_x(const float* __restrict__ x) {
    size_t i = (size_t)blockIdx.x * 256 + threadIdx.x;   // over elems/4
    float4 v = ((const float4*)x)[i];
    float vv[4] = {v.x, v.y, v.z, v.w};
#pragma unroll
    for (int p = 0; p < 2; p++) {
        float a = vv[2 * p], b = vv[2 * p + 1];
        __nv_bfloat16 bh0 = __float2bfloat16(a), bh1 = __float2bfloat16(b);
        ((__nv_bfloat162*)g_xh)[2 * i + p] = __halves2bfloat162(bh0, bh1);
        ((__nv_bfloat162*)g_xl)[2 * i + p] = __halves2bfloat162(
            __float2bfloat16(a - __bfloat162float(bh0)),
            __float2bfloat16(b - __bfloat162float(bh1)));
        __half fh0 = __float2half(a), fh1 = __float2half(b);
        ((__half2*)g_xfh)[2 * i + p] = __halves2half2(fh0, fh1);
        ((__half2*)g_xfl)[2 * i + p] = __halves2half2(
            __float2half(a - __half2float(fh0)),
            __float2half(b - __half2float(fh1)));
    }
}

// transpose + convert: out[n][k] = W[k][n].  z 0/1: bf16 hi/lo; z 2/3: fp16 single.
__global__ void conv_w(const float* __restrict__ Wq, const float* __restrict__ Wk,
                       const float* __restrict__ Wv, const float* __restrict__ Wo) {
    __shared__ float t[32][33];
    int z = blockIdx.z;
    const float* W = (z == 0) ? Wq : (z == 1) ? Wk : (z == 2) ? Wv : Wo;
    int bx = blockIdx.x * 32, by = blockIdx.y * 32;     // bx: n, by: k
    int tx = threadIdx.x, ty = threadIdx.y;
#pragma unroll
    for (int i = 0; i < 4; i++)
        t[ty + i * 8][tx] = W[(size_t)(by + ty + i * 8) * DMODEL + bx + tx];
    __syncthreads();
#pragma unroll
    for (int i = 0; i < 4; i++) {
        float v = t[tx][ty + i * 8];
        size_t oi = (size_t)(bx + ty + i * 8) * DMODEL + by + tx;
        if (z < 2) {
            __nv_bfloat16 h = __float2bfloat16(v);
            __nv_bfloat16 l = __float2bfloat16(v - __bfloat162float(h));
            if (z == 0) { g_wqh[oi] = h; g_wql[oi] = l; }
            else        { g_wkh[oi] = h; g_wkl[oi] = l; }
        } else {
            __half h = __float2half(v);
            if (z == 2) g_wvh[oi] = h;
            else        g_woh[oi] = h;
        }
    }
}

__global__ void rope_table() {
    int d = blockIdx.x;                                  // 0..63
    double invf = pow(10000.0, -(double)d / 64.0);
    const double TWO_PI = 6.283185307179586476925286766559;
    for (int s = threadIdx.x; s < CTXN; s += blockDim.x) {
        double a = (double)s * invf;
        double r = a - TWO_PI * floor(a / TWO_PI);
        float sn, cs;
        sincosf((float)r, &sn, &cs);
        g_rope[d * CTXN + s] = make_float2(sn, cs);
    }
}

// ======================= bf16 3-term GEMM core =============================
#define KC 32
#define SROW 40
#define MAT_BYTES (128 * SROW * 2)            // 10240
#define STAGE_BYTES (4 * MAT_BYTES)           // 40960
#define GEMM_SMEM (2 * STAGE_BYTES)           // 81920
#define NCHUNK (DMODEL / KC)                  // 64

__device__ __forceinline__ void load_stage(
    uint32_t sb, int kt,
    const __nv_bfloat16* __restrict__ Ah, const __nv_bfloat16* __restrict__ Al,
    const __nv_bfloat16* __restrict__ Bh, const __nv_bfloat16* __restrict__ Bl,
    int mBase, int nBase, int tid)
{
#pragma unroll
    for (int i = 0; i < 2; i++) {
        int fid = tid + i * 256;
        int row = fid >> 2, u = fid & 3;
        uint32_t off = (uint32_t)(row * (SROW * 2) + u * 16);
        size_t ga = (size_t)(mBase + row) * DMODEL + kt + u * 8;
        size_t gb = (size_t)(nBase + row) * DMODEL + kt + u * 8;
        cpa16(sb + off,                 &Ah[ga]);
        cpa16(sb + MAT_BYTES + off,     &Al[ga]);
        cpa16(sb + 2 * MAT_BYTES + off, &Bh[gb]);
        cpa16(sb + 3 * MAT_BYTES + off, &Bl[gb]);
    }
}

__device__ __forceinline__ void compute_stage(
    uint32_t sb, int wm, int wn2, int lane, float (&acc)[4][4][4])
{
    uint32_t Ab  = sb;
    uint32_t Alb = sb + MAT_BYTES;
    uint32_t Bb  = sb + 2 * MAT_BYTES;
    uint32_t Blb = sb + 3 * MAT_BYTES;
#pragma unroll
    for (int ks = 0; ks < KC / 16; ks++) {
        uint32_t ah[4][4], al[4][4];
#pragma unroll
        for (int i = 0; i < 4; i++) {
            uint32_t aoff = (uint32_t)(((wm + i * 16 + (lane & 15)) * SROW
                             + (lane >> 4) * 8 + ks * 16) * 2);
            ldsm4(ah[i], Ab + aoff);
            ldsm4(al[i], Alb + aoff);
        }
        uint32_t bh[2][4], bl[2][4];
#pragma unroll
        for (int jp = 0; jp < 2; jp++) {
            int bn = wn2 + jp * 64 + (lane & 7) + ((lane >> 4) & 1) * 8;
            int bk = ((lane >> 3) & 1) * 8 + ks * 16;
            uint32_t boff = (uint32_t)((bn * SROW + bk) * 2);
            ldsm4(bh[jp], Bb + boff);
            ldsm4(bl[jp], Blb + boff);
        }
#pragma unroll
        for (int i = 0; i < 4; i++) {
#pragma unroll
            for (int jp = 0; jp < 2; jp++) {
                mma_bf16(acc[i][jp * 2],     ah[i], &bh[jp][0]);
                mma_bf16(acc[i][jp * 2 + 1], ah[i], &bh[jp][2]);
                mma_bf16(acc[i][jp * 2],     ah[i], &bl[jp][0]);
                mma_bf16(acc[i][jp * 2 + 1], ah[i], &bl[jp][2]);
                mma_bf16(acc[i][jp * 2],     al[i], &bh[jp][0]);
                mma_bf16(acc[i][jp * 2 + 1], al[i], &bh[jp][2]);
            }
        }
    }
}

__device__ __forceinline__ void gemm_mainloop(
    const __nv_bfloat16* __restrict__ Ah, const __nv_bfloat16* __restrict__ Al,
    const __nv_bfloat16* __restrict__ Bh, const __nv_bfloat16* __restrict__ Bl,
    int mBase, int nBase, char* smem, float (&acc)[4][4][4])
{
    uint32_t smem_u = smem_to_u32(smem);
    const int tid = threadIdx.x;
    const int lane = tid & 31, wid = tid >> 5;
    const int wm = (wid >> 2) * 64, wn2 = (wid & 3) * 16;

#pragma unroll
    for (int i = 0; i < 4; i++)
#pragma unroll
        for (int j = 0; j < 4; j++)
#pragma unroll
            for (int r = 0; r < 4; r++) acc[i][j][r] = 0.f;

    load_stage(smem_u, 0, Ah, Al, Bh, Bl, mBase, nBase, tid);
    CP_COMMIT();

    for (int c = 0; c < NCHUNK; c++) {
        CP_WAIT(0);
        __syncthreads();
        if (c + 1 < NCHUNK) {
            load_stage(smem_u + (uint32_t)((c + 1) & 1) * STAGE_BYTES,
                       (c + 1) * KC, Ah, Al, Bh, Bl, mBase, nBase, tid);
            CP_COMMIT();
        }
        compute_stage(smem_u + (uint32_t)(c & 1) * STAGE_BYTES, wm, wn2, lane, acc);
    }
}

// ======================= fp16 2-term GEMM core =============================
#define STAGE_H (3 * MAT_BYTES)               // 30720
#define GEMM_H_SMEM (2 * STAGE_H)             // 61440

__device__ __forceinline__ void load_stage_h(
    uint32_t sb, int kt,
    const __half* __restrict__ Ah, const __half* __restrict__ Al,
    const __half* __restrict__ Bh,
    int mBase, int nBase, int tid)
{
#pragma unroll
    for (int i = 0; i < 2; i++) {
        int fid = tid + i * 256;
        int row = fid >> 2, u = fid & 3;
        uint32_t off = (uint32_t)(row * (SROW * 2) + u * 16);
        size_t ga = (size_t)(mBase + row) * DMODEL + kt + u * 8;
        size_t gb = (size_t)(nBase + row) * DMODEL + kt + u * 8;
        cpa16(sb + off,                 &Ah[ga]);
        cpa16(sb + MAT_BYTES + off,     &Al[ga]);
        cpa16(sb + 2 * MAT_BYTES + off, &Bh[gb]);
    }
}

__device__ __forceinline__ void compute_stage_h(
    uint32_t sb, int wm, int wn2, int lane, float (&acc)[4][4][4])
{
    uint32_t Ab  = sb;
    uint32_t Alb = sb + MAT_BYTES;
    uint32_t Bb  = sb + 2 * MAT_BYTES;
#pragma unroll
    for (int ks = 0; ks < KC / 16; ks++) {
        uint32_t ah[4][4], al[4][4];
#pragma unroll
        for (int i = 0; i < 4; i++) {
            uint32_t aoff = (uint32_t)(((wm + i * 16 + (lane & 15)) * SROW
                             + (lane >> 4) * 8 + ks * 16) * 2);
            ldsm4(ah[i], Ab + aoff);
            ldsm4(al[i], Alb + aoff);
        }
        uint32_t bh[2][4];
#pragma unroll
        for (int jp = 0; jp < 2; jp++) {
            int bn = wn2 + jp * 64 + (lane & 7) + ((lane >> 4) & 1) * 8;
            int bk = ((lane >> 3) & 1) * 8 + ks * 16;
            uint32_t boff = (uint32_t)((bn * SROW + bk) * 2);
            ldsm4(bh[jp], Bb + boff);
        }
#pragma unroll
        for (int i = 0; i < 4; i++) {
#pragma unroll
            for (int jp = 0; jp < 2; jp++) {
                mma_f16(acc[i][jp * 2],     ah[i], &bh[jp][0]);
                mma_f16(acc[i][jp * 2 + 1], ah[i], &bh[jp][2]);
                mma_f16(acc[i][jp * 2],     al[i], &bh[jp][0]);
                mma_f16(acc[i][jp * 2 + 1], al[i], &bh[jp][2]);
            }
        }
    }
}

__device__ __forceinline__ void gemm_mainloop_h(
    const __half* __restrict__ Ah, const __half* __restrict__ Al,
    const __half* __restrict__ Bh,
    int mBase, int nBase, char* smem, float (&acc)[4][4][4])
{
    uint32_t smem_u = smem_to_u32(smem);
    const int tid = threadIdx.x;
    const int lane = tid & 31, wid = tid >> 5;
    const int wm = (wid >> 2) * 64, wn2 = (wid & 3) * 16;

#pragma unroll
    for (int i = 0; i < 4; i++)
#pragma unroll
        for (int j = 0; j < 4; j++)
#pragma unroll
            for (int r = 0; r < 4; r++) acc[i][j][r] = 0.f;

    load_stage_h(smem_u, 0, Ah, Al, Bh, mBase, nBase, tid);
    CP_COMMIT();

    for (int c = 0; c < NCHUNK; c++) {
        CP_WAIT(0);
        __syncthreads();
        if (c + 1 < NCHUNK) {
            load_stage_h(smem_u + (uint32_t)((c + 1) & 1) * STAGE_H,
                         (c + 1) * KC, Ah, Al, Bh, mBase, nBase, tid);
            CP_COMMIT();
        }
        compute_stage_h(smem_u + (uint32_t)(c & 1) * STAGE_H, wm, wn2, lane, acc);
    }
}

// ======================= QKV GEMM (merged; z 0/1 = Q/K bf16, z 2 = V fp16) =
__global__ void __launch_bounds__(256, 2) qkv_tc() {
    extern __shared__ char smem[];
    const int z = blockIdx.z;
    const int mBase = blockIdx.y * 128, nBase = blockIdx.x * 128;
    const int head = blockIdx.x;
    const int tid = threadIdx.x;
    const int lane = tid & 31, wid = tid >> 5;
    const int wm = (wid >> 2) * 64, wn2 = (wid & 3) * 16;

    float acc[4][4][4];

    if (z < 2) {
        // ---- Q or K: bf16 3-term + fused RoPE ----
        const __nv_bfloat16* Bh_ = (z == 0) ? g_wqh : g_wkh;
        const __nv_bfloat16* Bl_ = (z == 0) ? g_wql : g_wkl;
        __nv_bfloat16* Dh = (z == 0) ? g_Qh : g_Kh;
        __nv_bfloat16* Dl = (z == 0) ? g_Ql : g_Kl;

        gemm_mainloop(g_xh, g_xl, Bh_, Bl_, mBase, nBase, smem, acc);

#pragma unroll
        for (int i = 0; i < 4; i++) {
            int gm0 = mBase + wm + i * 16 + (lane >> 2);
#pragma unroll
            for (int rr = 0; rr < 2; rr++) {
                int gm = gm0 + rr * 8;
                int b = gm >> 11, s = gm & (CTXN - 1);
                size_t base = (((size_t)b * NH + head) * CTXN + s) * HD;
#pragma unroll
                for (int jl = 0; jl < 2; jl++) {
                    int c = wn2 + jl * 8 + (lane & 3) * 2;
                    float lo0 = acc[i][jl][rr * 2 + 0];
                    float lo1 = acc[i][jl][rr * 2 + 1];
                    float hi0 = acc[i][jl + 2][rr * 2 + 0];
                    float hi1 = acc[i][jl + 2][rr * 2 + 1];
                    float2 sc0 = g_rope[c * CTXN + s];
                    float2 sc1 = g_rope[(c + 1) * CTXN + s];
                    float t0 = lo0 * sc0.y - hi0 * sc0.x;
                    float t2 = hi0 * sc0.y + lo0 * sc0.x;
                    float t1 = lo1 * sc1.y - hi1 * sc1.x;
                    float t3 = hi1 * sc1.y + lo1 * sc1.x;
                    lo0 = t0; lo1 = t1; hi0 = t2; hi1 = t3;
                    __nv_bfloat16 a0 = __float2bfloat16(lo0), a1 = __float2bfloat16(lo1);
                    __nv_bfloat16 b0 = __float2bfloat16(hi0), b1 = __float2bfloat16(hi1);
                    *(__nv_bfloat162*)&Dh[base + c]      = __halves2bfloat162(a0, a1);
                    *(__nv_bfloat162*)&Dh[base + c + 64] = __halves2bfloat162(b0, b1);
                    *(__nv_bfloat162*)&Dl[base + c]      = __halves2bfloat162(
                        __float2bfloat16(lo0 - __bfloat162float(a0)),
                        __float2bfloat16(lo1 - __bfloat162float(a1)));
                    *(__nv_bfloat162*)&Dl[base + c + 64] = __halves2bfloat162(
                        __float2bfloat16(hi0 - __bfloat162float(b0)),
                        __float2bfloat16(hi1 - __bfloat162float(b1)));
                }
            }
        }
    } else {
        // ---- V: fp16 2-term, fp16 hi/lo out ----
        gemm_mainloop_h(g_xfh, g_xfl, g_wvh, mBase, nBase, smem, acc);

#pragma unroll
        for (int i = 0; i < 4; i++) {
            int gm0 = mBase + wm + i * 16 + (lane >> 2);
#pragma unroll
            for (int rr = 0; rr < 2; rr++) {
                int gm = gm0 + rr * 8;
                int b = gm >> 11, s = gm & (CTXN - 1);
                size_t base = (((size_t)b * NH + head) * CTXN + s) * HD;
#pragma unroll
                for (int jl = 0; jl < 2; jl++) {
                    int c = wn2 + jl * 8 + (lane & 3) * 2;
                    float lo0 = acc[i][jl][rr * 2 + 0];
                    float lo1 = acc[i][jl][rr * 2 + 1];
                    float hi0 = acc[i][jl + 2][rr * 2 + 0];
                    float hi1 = acc[i][jl + 2][rr * 2 + 1];
                    __half a0 = __float2half(lo0), a1 = __float2half(lo1);
                    __half b0 = __float2half(hi0), b1 = __float2half(hi1);
                    *(__half2*)&g_Vh[base + c]      = __halves2half2(a0, a1);
                    *(__half2*)&g_Vh[base + c + 64] = __halves2half2(b0, b1);
                    *(__half2*)&g_Vl[base + c]      = __halves2half2(
                        __float2half(lo0 - __half2float(a0)),
                        __float2half(lo1 - __half2float(a1)));
                    *(__half2*)&g_Vl[base + c + 64] = __halves2half2(
                        __float2half(hi0 - __half2float(b0)),
                        __float2half(hi1 - __half2float(b1)));
                }
            }
        }
    }
}

// ======================= output projection (fp16 2-term) ===================
__global__ void __launch_bounds__(256, 2) out_tc(float* __restrict__ out) {
    extern __shared__ char smem[];
    const int mBase = blockIdx.y * 128, nBase = blockIdx.x * 128;

    float acc[4][4][4];
    gemm_mainloop_h(g_ctxh, g_ctxl, g_woh, mBase, nBase, smem, acc);

    const int tid = threadIdx.x;
    const int lane = tid & 31, wid = tid >> 5;
    const int wm = (wid >> 2) * 64, wn2 = (wid & 3) * 16;

#pragma unroll
    for (int i = 0; i < 4; i++) {
        int gm0 = mBase + wm + i * 16 + (lane >> 2);
#pragma unroll
        for (int rr = 0; rr < 2; rr++) {
            int gm = gm0 + rr * 8;
            size_t rb = (size_t)gm * DMODEL + nBase;
#pragma unroll
            for (int jl = 0; jl < 2; jl++) {
                int c = wn2 + jl * 8 + (lane & 3) * 2;
                *(float2*)&out[rb + c] =
                    make_float2(acc[i][jl][rr * 2], acc[i][jl][rr * 2 + 1]);
                *(float2*)&out[rb + c + 64] =
                    make_float2(acc[i][jl + 2][rr * 2], acc[i][jl + 2][rr * 2 + 1]);
            }
        }
    }
}

// ======================= tensor-core flash attention =======================
#define SA 136
#define AQH 0
#define AQL (128 * SA * 2)
#define ASTAGE0 (2 * 128 * SA * 2)               // 69632
#define ASTG (4 * 64 * SA * 2)                   // 69632 per stage
#define AKH 0
#define AKL (64 * SA * 2)
#define AVH (2 * 64 * SA * 2)
#define AVL (3 * 64 * SA * 2)
#define ATTN2_SMEM (ASTAGE0 + 2 * ASTG)          // 208896

__device__ __forceinline__ void load_kv_tile(uint32_t dst, size_t bhoff,
                                             int kvrow, int tid) {
#pragma unroll
    for (int i = 0; i < 4; i++) {
        int cid = tid + i * 256;
        int row = cid >> 4, u = cid & 15;
        uint32_t off = (uint32_t)(row * (SA * 2) + u * 16);
        size_t g = bhoff + (size_t)(kvrow + row) * HD + u * 8;
        cpa16(dst + AKH + off, &g_Kh[g]);
        cpa16(dst + AKL + off, &g_Kl[g]);
        cpa16(dst + AVH + off, &g_Vh[g]);
        cpa16(dst + AVL + off, &g_Vl[g]);
    }
}

__global__ void __launch_bounds__(256, 1) attn_tc() {
    extern __shared__ char smc[];
    uint32_t su = smem_to_u32(smc);
    const int tid = threadIdx.x, lane = tid & 31, wid = tid >> 5;
    const int qt = 15 - (int)blockIdx.x;
    const int bh = blockIdx.y;
    const int b = bh >> 4, h = bh & 15;
    const size_t bhoff = (size_t)bh * CTXN * HD;
    const int qbase = qt * 128;
    const int wm = wid * 16;
    const int ntiles = 2 * qt + 2;

#pragma unroll
    for (int i = 0; i < 8; i++) {
        int cid = tid + i * 256;
        int row = cid >> 4, u = cid & 15;
        uint32_t off = (uint32_t)(row * (SA * 2) + u * 16);
        size_t g = bhoff + (size_t)(qbase + row) * HD + u * 8;
        cpa16(su + AQH + off, &g_Qh[g]);
        cpa16(su + AQL + off, &g_Ql[g]);
    }
    load_kv_tile(su + ASTAGE0, bhoff, 0, tid);
    CP_COMMIT();

    float oacc[16][4];
#pragma unroll
    for (int i = 0; i < 16; i++)
#pragma unroll
        for (int r = 0; r < 4; r++) oacc[i][r] = 0.f;
    float m0 = -INFINITY, m1 = -INFINITY, l0 = 0.f, l1 = 0.f;

    for (int j = 0; j < ntiles; j++) {
        int buf = j & 1;
        CP_WAIT(0);
        __syncthreads();
        if (j + 1 < ntiles) {
            load_kv_tile(su + ASTAGE0 + (uint32_t)(buf ^ 1) * ASTG,
                         bhoff, (j + 1) * 64, tid);
            CP_COMMIT();
        }
        const int kvbase = j * 64;
        if (kvbase <= qbase + wm + 15) {
            uint32_t kbh = su + ASTAGE0 + (uint32_t)buf * ASTG + AKH;
            uint32_t kbl = kbh + (AKL - AKH);
            uint32_t vbh = su + ASTAGE0 + (uint32_t)buf * ASTG + AVH;
            uint32_t vbl = vbh + (AVL - AVH);

            float sacc[8][4];
#pragma unroll
            for (int i = 0; i < 8; i++)
#pragma unroll
                for (int r = 0; r < 4; r++) sacc[i][r] = 0.f;
#pragma unroll
            for (int ks = 0; ks < 8; ks++) {
                uint32_t ah[4], al[4];
                uint32_t aoff = (uint32_t)(((wm + (lane & 15)) * SA
                                 + (lane >> 4) * 8 + ks * 16) * 2);
                ldsm4(ah, su + AQH + aoff);
                ldsm4(al, su + AQL + aoff);
#pragma unroll
                for (int jp = 0; jp < 4; jp++) {
                    int bn = jp * 16 + (lane & 7) + ((lane >> 4) & 1) * 8;
                    int bk = ((lane >> 3) & 1) * 8 + ks * 16;
                    uint32_t boff = (uint32_t)((bn * SA + bk) * 2);
                    uint32_t kh4[4], kl4[4];
                    ldsm4(kh4, kbh + boff);
                    ldsm4(kl4, kbl + boff);
                    mma_bf16(sacc[jp * 2],     ah, &kh4[0]);
                    mma_bf16(sacc[jp * 2 + 1], ah, &kh4[2]);
                    mma_bf16(sacc[jp * 2],     ah, &kl4[0]);
                    mma_bf16(sacc[jp * 2 + 1], ah, &kl4[2]);
                    mma_bf16(sacc[jp * 2],     al, &kh4[0]);
                    mma_bf16(sacc[jp * 2 + 1], al, &kh4[2]);
                }
            }

            if (kvbase + 63 > qbase + wm) {
                int row0 = qbase + wm + (lane >> 2);
                int c0 = kvbase + (lane & 3) * 2;
#pragma unroll
                for (int nb = 0; nb < 8; nb++) {
                    int c = c0 + nb * 8;
                    if (c     > row0)     sacc[nb][0] = -1e30f;
                    if (c + 1 > row0)     sacc[nb][1] = -1e30f;
                    if (c     > row0 + 8) sacc[nb][2] = -1e30f;
                    if (c + 1 > row0 + 8) sacc[nb][3] = -1e30f;
                }
            }

            float mx0 = -INFINITY, mx1 = -INFINITY;
#pragma unroll
            for (int nb = 0; nb < 8; nb++) {
                mx0 = fmaxf(mx0, fmaxf(sacc[nb][0], sacc[nb][1]));
                mx1 = fmaxf(mx1, fmaxf(sacc[nb][2], sacc[nb][3]));
            }
            mx0 = fmaxf(mx0, __shfl_xor_sync(0xffffffffu, mx0, 1));
            mx0 = fmaxf(mx0, __shfl_xor_sync(0xffffffffu, mx0, 2));
            mx1 = fmaxf(mx1, __shfl_xor_sync(0xffffffffu, mx1, 1));
            mx1 = fmaxf(mx1, __shfl_xor_sync(0xffffffffu, mx1, 2));
            float mn0 = fmaxf(m0, mx0), mn1 = fmaxf(m1, mx1);
            float a0 = __expf(m0 - mn0), a1 = __expf(m1 - mn1);
            m0 = mn0; m1 = mn1;
            float s0 = 0.f, s1 = 0.f;
#pragma unroll
            for (int nb = 0; nb < 8; nb++) {
                float p0 = __expf(sacc[nb][0] - mn0);
                float p1 = __expf(sacc[nb][1] - mn0);
                float p2 = __expf(sacc[nb][2] - mn1);
                float p3 = __expf(sacc[nb][3] - mn1);
                sacc[nb][0] = p0; sacc[nb][1] = p1;
                sacc[nb][2] = p2; sacc[nb][3] = p3;
                s0 += p0 + p1; s1 += p2 + p3;
            }
            s0 += __shfl_xor_sync(0xffffffffu, s0, 1);
            s0 += __shfl_xor_sync(0xffffffffu, s0, 2);
            s1 += __shfl_xor_sync(0xffffffffu, s1, 1);
            s1 += __shfl_xor_sync(0xffffffffu, s1, 2);
            l0 = l0 * a0 + s0;
            l1 = l1 * a1 + s1;
#pragma unroll
            for (int i = 0; i < 16; i++) {
                oacc[i][0] *= a0; oacc[i][1] *= a0;
                oacc[i][2] *= a1; oacc[i][3] *= a1;
            }

#pragma unroll
            for (int kb = 0; kb < 4; kb++) {
                uint32_t ph[4];
                ph[0] = pack_h16(sacc[2 * kb][0],     sacc[2 * kb][1]);
                ph[1] = pack_h16(sacc[2 * kb][2],     sacc[2 * kb][3]);
                ph[2] = pack_h16(sacc[2 * kb + 1][0], sacc[2 * kb + 1][1]);
                ph[3] = pack_h16(sacc[2 * kb + 1][2], sacc[2 * kb + 1][3]);
#pragma unroll
                for (int jn = 0; jn < 8; jn++) {
                    uint32_t voff = (uint32_t)(((kb * 16 + (lane & 15)) * SA
                                     + jn * 16 + (lane >> 4) * 8) * 2);
                    uint32_t vh4[4], vl4[4];
                    ldsm4t(vh4, vbh + voff);
                    ldsm4t(vl4, vbl + voff);
                    mma_f16(oacc[jn * 2],     ph, &vh4[0]);
                    mma_f16(oacc[jn * 2 + 1], ph, &vh4[2]);
                    mma_f16(oacc[jn * 2],     ph, &vl4[0]);
                    mma_f16(oacc[jn * 2 + 1], ph, &vl4[2]);
                }
            }
        }
    }

    float inv0 = 1.0f / l0, inv1 = 1.0f / l1;
    int sr0 = qbase + wm + (lane >> 2);
    size_t r0i = ((size_t)(b * CTXN + sr0)) * DMODEL + h * HD;
    size_t r1i = r0i + (size_t)8 * DMODEL;
#pragma unroll
    for (int jn = 0; jn < 16; jn++) {
        int c = jn * 8 + (lane & 3) * 2;
        float v0 = oacc[jn][0] * inv0, v1 = oacc[jn][1] * inv0;
        float v2 = oacc[jn][2] * inv1, v3 = oacc[jn][3] * inv1;
        __half h0a = __float2half(v0), h0b = __float2half(v1);
        __half h1a = __float2half(v2), h1b = __float2half(v3);
        *(__half2*)&g_ctxh[r0i + c] = __halves2half2(h0a, h0b);
        *(__half2*)&g_ctxh[r1i + c] = __halves2half2(h1a, h1b);
        *(__half2*)&g_ctxl[r0i + c] = __halves2half2(
            __float2half(v0 - __half2float(h0a)),
            __float2half(v1 - __half2float(h0b)));
        *(__half2*)&g_ctxl[r1i + c] = __halves2half2(
            __float2half(v2 - __half2float(h1a)),
            __float2half(v3 - __half2float(h1b)));
    }
}

// ======================= launch ============================================
extern "C" void kernel_launch(void* const* d_in, const int* in_sizes, int n_in,
                              void* d_out, int out_size)
{
    (void)in_sizes; (void)n_in; (void)out_size;
    const float* x  = (const float*)d_in[0];
    const float* Wq = (const float*)d_in[1];
    const float* Wk = (const float*)d_in[2];
    const float* Wv = (const float*)d_in[3];
    const float* Wo = (const float*)d_in[4];
    float* out = (float*)d_out;

    cudaFuncSetAttribute(qkv_tc,  cudaFuncAttributeMaxDynamicSharedMemorySize, GEMM_SMEM);
    cudaFuncSetAttribute(out_tc,  cudaFuncAttributeMaxDynamicSharedMemorySize, GEMM_H_SMEM);
    cudaFuncSetAttribute(attn_tc, cudaFuncAttributeMaxDynamicSharedMemorySize, ATTN2_SMEM);

    conv_x<<<(MROWS * DMODEL / 4) / 256, 256>>>(x);
    conv_w<<<dim3(64, 64, 4), dim3(32, 8)>>>(Wq, Wk, Wv, Wo);
    rope_table<<<64, 256>>>();
    qkv_tc<<<dim3(DMODEL / 128, MROWS / 128, 3), 256, GEMM_SMEM>>>();
    attn_tc<<<dim3(16, 32), 256, ATTN2_SMEM>>>();
    out_tc<<<dim3(DMODEL / 128, MROWS / 128), 256, GEMM_H_SMEM>>>(out);
}

// round 16
// speedup vs baseline: 1.0869x; 1.0061x over previous
#include <cuda_runtime.h>
#include <cuda_bf16.h>
#include <cuda_fp16.h>
#include <cstdint>
#include <math.h>

#define CTXN   2048
#define DMODEL 2048
#define NH     16
#define HD     128
#define BSZ    2
#define MROWS  (BSZ * CTXN)   // 4096

// ---------------- scratch (device globals; no allocation allowed) ----------
__device__ __nv_bfloat16 g_xh[MROWS * DMODEL];     // x bf16 hi/lo (QK proj)
__device__ __nv_bfloat16 g_xl[MROWS * DMODEL];
__device__ __half        g_xfh[MROWS * DMODEL];    // x fp16 hi/lo (V proj)
__device__ __half        g_xfl[MROWS * DMODEL];
__device__ __nv_bfloat16 g_wqh[DMODEL * DMODEL], g_wql[DMODEL * DMODEL];
__device__ __nv_bfloat16 g_wkh[DMODEL * DMODEL], g_wkl[DMODEL * DMODEL];
__device__ __half        g_wvh[DMODEL * DMODEL];   // Wv fp16 single
__device__ __half        g_woh[DMODEL * DMODEL];   // Wo fp16 single
__device__ __nv_bfloat16 g_Qh[BSZ * NH * CTXN * HD], g_Ql[BSZ * NH * CTXN * HD];
__device__ __nv_bfloat16 g_Kh[BSZ * NH * CTXN * HD], g_Kl[BSZ * NH * CTXN * HD];
__device__ __half        g_Vh[BSZ * NH * CTXN * HD], g_Vl[BSZ * NH * CTXN * HD];
__device__ __half        g_ctxh[MROWS * DMODEL];   // ctx fp16 hi/lo
__device__ __half        g_ctxl[MROWS * DMODEL];
__device__ float2 g_rope[64 * CTXN];               // [d][s] (sin, cos)

// ======================= low-level helpers =================================
__device__ __forceinline__ uint32_t smem_to_u32(const void* p) {
    uint32_t a;
    asm("{ .reg .u64 t; cvta.to.shared.u64 t, %1; cvt.u32.u64 %0, t; }"
        : "=r"(a) : "l"(p));
    return a;
}
__device__ __forceinline__ void cpa16(uint32_t dst, const void* src) {
    asm volatile("cp.async.cg.shared.global [%0], [%1], 16;" :: "r"(dst), "l"(src));
}
#define CP_COMMIT() asm volatile("cp.async.commit_group;" ::: "memory")
#define CP_WAIT(n)  asm volatile("cp.async.wait_group %0;" :: "n"(n) : "memory")

__device__ __forceinline__ void ldsm4(uint32_t* r, uint32_t addr) {
    asm volatile("ldmatrix.sync.aligned.m8n8.x4.shared.b16 {%0,%1,%2,%3}, [%4];"
        : "=r"(r[0]), "=r"(r[1]), "=r"(r[2]), "=r"(r[3]) : "r"(addr));
}
__device__ __forceinline__ void ldsm4t(uint32_t* r, uint32_t addr) {
    asm volatile("ldmatrix.sync.aligned.m8n8.x4.trans.shared.b16 {%0,%1,%2,%3}, [%4];"
        : "=r"(r[0]), "=r"(r[1]), "=r"(r[2]), "=r"(r[3]) : "r"(addr));
}
__device__ __forceinline__ void mma_bf16(float* d, const uint32_t* a, const uint32_t* b) {
    asm volatile(
        "mma.sync.aligned.m16n8k16.row.col.f32.bf16.bf16.f32 "
        "{%0,%1,%2,%3}, {%4,%5,%6,%7}, {%8,%9}, {%0,%1,%2,%3};"
        : "+f"(d[0]), "+f"(d[1]), "+f"(d[2]), "+f"(d[3])
        : "r"(a[0]), "r"(a[1]), "r"(a[2]), "r"(a[3]), "r"(b[0]), "r"(b[1]));
}
__device__ __forceinline__ void mma_f16(float* d, const uint32_t* a, const uint32_t* b) {
    asm volatile(
        "mma.sync.aligned.m16n8k16.row.col.f32.f16.f16.f32 "
        "{%0,%1,%2,%3}, {%4,%5,%6,%7}, {%8,%9}, {%0,%1,%2,%3};"
        : "+f"(d[0]), "+f"(d[1]), "+f"(d[2]), "+f"(d[3])
        : "r"(a[0]), "r"(a[1]), "r"(a[2]), "r"(a[3]), "r"(b[0]), "r"(b[1]));
}
__device__ __forceinline__ uint32_t pack_h16(float a, float b) {
    __half2 p = __halves2half2(__float2half(a), __float2half(b));
    return *(uint32_t*)&p;
}

// ======================= prep kernels ======================================
__global__ void conv_x(const float* __restrict__ x) {
    size_t i = (size_t)blockIdx.x * 256 + threadIdx.x;   // over elems/4
    float4 v = ((const float4*)x)[i];
    float vv[4] = {v.x, v.y, v.z, v.w};
#pragma unroll
    for (int p = 0; p < 2; p++) {
        float a = vv[2 * p], b = vv[2 * p + 1];
        __nv_bfloat16 bh0 = __float2bfloat16(a), bh1 = __float2bfloat16(b);
        ((__nv_bfloat162*)g_xh)[2 * i + p] = __halves2bfloat162(bh0, bh1);
        ((__nv_bfloat162*)g_xl)[2 * i + p] = __halves2bfloat162(
            __float2bfloat16(a - __bfloat162float(bh0)),
            __float2bfloat16(b - __bfloat162float(bh1)));
        __half fh0 = __float2half(a), fh1 = __float2half(b);
        ((__half2*)g_xfh)[2 * i + p] = __halves2half2(fh0, fh1);
        ((__half2*)g_xfl)[2 * i + p] = __halves2half2(
            __float2half(a - __half2float(fh0)),
            __float2half(b - __half2float(fh1)));
    }
}

// transpose + convert: out[n][k] = W[k][n].  z 0/1: bf16 hi/lo; z 2/3: fp16 single.
__global__ void conv_w(const float* __restrict__ Wq, const float* __restrict__ Wk,
                       const float* __restrict__ Wv, const float* __restrict__ Wo) {
    __shared__ float t[32][33];
    int z = blockIdx.z;
    const float* W = (z == 0) ? Wq : (z == 1) ? Wk : (z == 2) ? Wv : Wo;
    int bx = blockIdx.x * 32, by = blockIdx.y * 32;     // bx: n, by: k
    int tx = threadIdx.x, ty = threadIdx.y;
#pragma unroll
    for (int i = 0; i < 4; i++)
        t[ty + i * 8][tx] = W[(size_t)(by + ty + i * 8) * DMODEL + bx + tx];
    __syncthreads();
#pragma unroll
    for (int i = 0; i < 4; i++) {
        float v = t[tx][ty + i * 8];
        size_t oi = (size_t)(bx + ty + i * 8) * DMODEL + by + tx;
        if (z < 2) {
            __nv_bfloat16 h = __float2bfloat16(v);
            __nv_bfloat16 l = __float2bfloat16(v - __bfloat162float(h));
            if (z == 0) { g_wqh[oi] = h; g_wql[oi] = l; }
            else        { g_wkh[oi] = h; g_wkl[oi] = l; }
        } else {
            __half h = __float2half(v);
            if (z == 2) g_wvh[oi] = h;
            else        g_woh[oi] = h;
        }
    }
}

__global__ void rope_table() {
    int d = blockIdx.x;                                  // 0..63
    double invf = pow(10000.0, -(double)d / 64.0);
    const double TWO_PI = 6.283185307179586476925286766559;
    for (int s = threadIdx.x; s < CTXN; s += blockDim.x) {
        double a = (double)s * invf;
        double r = a - TWO_PI * floor(a / TWO_PI);
        float sn, cs;
        sincosf((float)r, &sn, &cs);
        g_rope[d * CTXN + s] = make_float2(sn, cs);
    }
}

// ======================= bf16 3-term GEMM core =============================
#define KC 32
#define SROW 40
#define MAT_BYTES (128 * SROW * 2)            // 10240
#define STAGE_BYTES (4 * MAT_BYTES)           // 40960
#define GEMM_SMEM (2 * STAGE_BYTES)           // 81920
#define NCHUNK (DMODEL / KC)                  // 64

__device__ __forceinline__ void load_stage(
    uint32_t sb, int kt,
    const __nv_bfloat16* __restrict__ Ah, const __nv_bfloat16* __restrict__ Al,
    const __nv_bfloat16* __restrict__ Bh, const __nv_bfloat16* __restrict__ Bl,
    int mBase, int nBase, int tid)
{
#pragma unroll
    for (int i = 0; i < 2; i++) {
        int fid = tid + i * 256;
        int row = fid >> 2, u = fid & 3;
        uint32_t off = (uint32_t)(row * (SROW * 2) + u * 16);
        size_t ga = (size_t)(mBase + row) * DMODEL + kt + u * 8;
        size_t gb = (size_t)(nBase + row) * DMODEL + kt + u * 8;
        cpa16(sb + off,                 &Ah[ga]);
        cpa16(sb + MAT_BYTES + off,     &Al[ga]);
        cpa16(sb + 2 * MAT_BYTES + off, &Bh[gb]);
        cpa16(sb + 3 * MAT_BYTES + off, &Bl[gb]);
    }
}

__device__ __forceinline__ void compute_stage(
    uint32_t sb, int wm, int wn2, int lane, float (&acc)[4][4][4])
{
    uint32_t Ab  = sb;
    uint32_t Alb = sb + MAT_BYTES;
    uint32_t Bb  = sb + 2 * MAT_BYTES;
    uint32_t Blb = sb + 3 * MAT_BYTES;
#pragma unroll
    for (int ks = 0; ks < KC / 16; ks++) {
        uint32_t ah[4][4], al[4][4];
#pragma unroll
        for (int i = 0; i < 4; i++) {
            uint32_t aoff = (uint32_t)(((wm + i * 16 + (lane & 15)) * SROW
                             + (lane >> 4) * 8 + ks * 16) * 2);
            ldsm4(ah[i], Ab + aoff);
            ldsm4(al[i], Alb + aoff);
        }
        uint32_t bh[2][4], bl[2][4];
#pragma unroll
        for (int jp = 0; jp < 2; jp++) {
            int bn = wn2 + jp * 64 + (lane & 7) + ((lane >> 4) & 1) * 8;
            int bk = ((lane >> 3) & 1) * 8 + ks * 16;
            uint32_t boff = (uint32_t)((bn * SROW + bk) * 2);
            ldsm4(bh[jp], Bb + boff);
            ldsm4(bl[jp], Blb + boff);
        }
#pragma unroll
        for (int i = 0; i < 4; i++) {
#pragma unroll
            for (int jp = 0; jp < 2; jp++) {
                mma_bf16(acc[i][jp * 2],     ah[i], &bh[jp][0]);
                mma_bf16(acc[i][jp * 2 + 1], ah[i], &bh[jp][2]);
                mma_bf16(acc[i][jp * 2],     ah[i], &bl[jp][0]);
                mma_bf16(acc[i][jp * 2 + 1], ah[i], &bl[jp][2]);
                mma_bf16(acc[i][jp * 2],     al[i], &bh[jp][0]);
                mma_bf16(acc[i][jp * 2 + 1], al[i], &bh[jp][2]);
            }
        }
    }
}

__device__ __forceinline__ void gemm_mainloop(
    const __nv_bfloat16* __restrict__ Ah, const __nv_bfloat16* __restrict__ Al,
    const __nv_bfloat16* __restrict__ Bh, const __nv_bfloat16* __restrict__ Bl,
    int mBase, int nBase, char* smem, float (&acc)[4][4][4])
{
    uint32_t smem_u = smem_to_u32(smem);
    const int tid = threadIdx.x;
    const int lane = tid & 31, wid = tid >> 5;
    const int wm = (wid >> 2) * 64, wn2 = (wid & 3) * 16;

#pragma unroll
    for (int i = 0; i < 4; i++)
#pragma unroll
        for (int j = 0; j < 4; j++)
#pragma unroll
            for (int r = 0; r < 4; r++) acc[i][j][r] = 0.f;

    load_stage(smem_u, 0, Ah, Al, Bh, Bl, mBase, nBase, tid);
    CP_COMMIT();

    for (int c = 0; c < NCHUNK; c++) {
        CP_WAIT(0);
        __syncthreads();
        if (c + 1 < NCHUNK) {
            load_stage(smem_u + (uint32_t)((c + 1) & 1) * STAGE_BYTES,
                       (c + 1) * KC, Ah, Al, Bh, Bl, mBase, nBase, tid);
            CP_COMMIT();
        }
        compute_stage(smem_u + (uint32_t)(c & 1) * STAGE_BYTES, wm, wn2, lane, acc);
    }
}

// ======================= fp16 2-term GEMM core =============================
#define STAGE_H (3 * MAT_BYTES)               // 30720
#define GEMM_H_SMEM (2 * STAGE_H)             // 61440

__device__ __forceinline__ void load_stage_h(
    uint32_t sb, int kt,
    const __half* __restrict__ Ah, const __half* __restrict__ Al,
    const __half* __restrict__ Bh,
    int mBase, int nBase, int tid)
{
#pragma unroll
    for (int i = 0; i < 2; i++) {
        int fid = tid + i * 256;
        int row = fid >> 2, u = fid & 3;
        uint32_t off = (uint32_t)(row * (SROW * 2) + u * 16);
        size_t ga = (size_t)(mBase + row) * DMODEL + kt + u * 8;
        size_t gb = (size_t)(nBase + row) * DMODEL + kt + u * 8;
        cpa16(sb + off,                 &Ah[ga]);
        cpa16(sb + MAT_BYTES + off,     &Al[ga]);
        cpa16(sb + 2 * MAT_BYTES + off, &Bh[gb]);
    }
}

__device__ __forceinline__ void compute_stage_h(
    uint32_t sb, int wm, int wn2, int lane, float (&acc)[4][4][4])
{
    uint32_t Ab  = sb;
    uint32_t Alb = sb + MAT_BYTES;
    uint32_t Bb  = sb + 2 * MAT_BYTES;
#pragma unroll
    for (int ks = 0; ks < KC / 16; ks++) {
        uint32_t ah[4][4], al[4][4];
#pragma unroll
        for (int i = 0; i < 4; i++) {
            uint32_t aoff = (uint32_t)(((wm + i * 16 + (lane & 15)) * SROW
                             + (lane >> 4) * 8 + ks * 16) * 2);
            ldsm4(ah[i], Ab + aoff);
            ldsm4(al[i], Alb + aoff);
        }
        uint32_t bh[2][4];
#pragma unroll
        for (int jp = 0; jp < 2; jp++) {
            int bn = wn2 + jp * 64 + (lane & 7) + ((lane >> 4) & 1) * 8;
            int bk = ((lane >> 3) & 1) * 8 + ks * 16;
            uint32_t boff = (uint32_t)((bn * SROW + bk) * 2);
            ldsm4(bh[jp], Bb + boff);
        }
#pragma unroll
        for (int i = 0; i < 4; i++) {
#pragma unroll
            for (int jp = 0; jp < 2; jp++) {
                mma_f16(acc[i][jp * 2],     ah[i], &bh[jp][0]);
                mma_f16(acc[i][jp * 2 + 1], ah[i], &bh[jp][2]);
                mma_f16(acc[i][jp * 2],     al[i], &bh[jp][0]);
                mma_f16(acc[i][jp * 2 + 1], al[i], &bh[jp][2]);
            }
        }
    }
}

__device__ __forceinline__ void gemm_mainloop_h(
    const __half* __restrict__ Ah, const __half* __restrict__ Al,
    const __half* __restrict__ Bh,
    int mBase, int nBase, char* smem, float (&acc)[4][4][4])
{
    uint32_t smem_u = smem_to_u32(smem);
    const int tid = threadIdx.x;
    const int lane = tid & 31, wid = tid >> 5;
    const int wm = (wid >> 2) * 64, wn2 = (wid & 3) * 16;

#pragma unroll
    for (int i = 0; i < 4; i++)
#pragma unroll
        for (int j = 0; j < 4; j++)
#pragma unroll
            for (int r = 0; r < 4; r++) acc[i][j][r] = 0.f;

    load_stage_h(smem_u, 0, Ah, Al, Bh, mBase, nBase, tid);
    CP_COMMIT();

    for (int c = 0; c < NCHUNK; c++) {
        CP_WAIT(0);
        __syncthreads();
        if (c + 1 < NCHUNK) {
            load_stage_h(smem_u + (uint32_t)((c + 1) & 1) * STAGE_H,
                         (c + 1) * KC, Ah, Al, Bh, mBase, nBase, tid);
            CP_COMMIT();
        }
        compute_stage_h(smem_u + (uint32_t)(c & 1) * STAGE_H, wm, wn2, lane, acc);
    }
}

// ======================= QK GEMM (+ fused RoPE, bf16 hi/lo out) ============
__global__ void __launch_bounds__(256, 2) qk_tc() {
    extern __shared__ char smem[];
    const int z = blockIdx.z;                    // 0=Q, 1=K
    const __nv_bfloat16* Bh_ = (z == 0) ? g_wqh : g_wkh;
    const __nv_bfloat16* Bl_ = (z == 0) ? g_wql : g_wkl;
    __nv_bfloat16* Dh = (z == 0) ? g_Qh : g_Kh;
    __nv_bfloat16* Dl = (z == 0) ? g_Ql : g_Kl;
    const int mBase = blockIdx.y * 128, nBase = blockIdx.x * 128;
    const int head = blockIdx.x;

    float acc[4][4][4];
    gemm_mainloop(g_xh, g_xl, Bh_, Bl_, mBase, nBase, smem, acc);

    const int tid = threadIdx.x;
    const int lane = tid & 31, wid = tid >> 5;
    const int wm = (wid >> 2) * 64, wn2 = (wid & 3) * 16;

#pragma unroll
    for (int i = 0; i < 4; i++) {
        int gm0 = mBase + wm + i * 16 + (lane >> 2);
#pragma unroll
        for (int rr = 0; rr < 2; rr++) {
            int gm = gm0 + rr * 8;
            int b = gm >> 11, s = gm & (CTXN - 1);
            size_t base = (((size_t)b * NH + head) * CTXN + s) * HD;
#pragma unroll
            for (int jl = 0; jl < 2; jl++) {
                int c = wn2 + jl * 8 + (lane & 3) * 2;
                float lo0 = acc[i][jl][rr * 2 + 0];
                float lo1 = acc[i][jl][rr * 2 + 1];
                float hi0 = acc[i][jl + 2][rr * 2 + 0];
                float hi1 = acc[i][jl + 2][rr * 2 + 1];
                float2 sc0 = g_rope[c * CTXN + s];
                float2 sc1 = g_rope[(c + 1) * CTXN + s];
                float t0 = lo0 * sc0.y - hi0 * sc0.x;
                float t2 = hi0 * sc0.y + lo0 * sc0.x;
                float t1 = lo1 * sc1.y - hi1 * sc1.x;
                float t3 = hi1 * sc1.y + lo1 * sc1.x;
                lo0 = t0; lo1 = t1; hi0 = t2; hi1 = t3;
                __nv_bfloat16 a0 = __float2bfloat16(lo0), a1 = __float2bfloat16(lo1);
                __nv_bfloat16 b0 = __float2bfloat16(hi0), b1 = __float2bfloat16(hi1);
                *(__nv_bfloat162*)&Dh[base + c]      = __halves2bfloat162(a0, a1);
                *(__nv_bfloat162*)&Dh[base + c + 64] = __halves2bfloat162(b0, b1);
                *(__nv_bfloat162*)&Dl[base + c]      = __halves2bfloat162(
                    __float2bfloat16(lo0 - __bfloat162float(a0)),
                    __float2bfloat16(lo1 - __bfloat162float(a1)));
                *(__nv_bfloat162*)&Dl[base + c + 64] = __halves2bfloat162(
                    __float2bfloat16(hi0 - __bfloat162float(b0)),
                    __float2bfloat16(hi1 - __bfloat162float(b1)));
            }
        }
    }
}

// ======================= V GEMM (fp16 2-term, fp16 hi/lo out) ==============
__global__ void __launch_bounds__(256, 2) v_tc() {
    extern __shared__ char smem[];
    const int mBase = blockIdx.y * 128, nBase = blockIdx.x * 128;
    const int head = blockIdx.x;

    float acc[4][4][4];
    gemm_mainloop_h(g_xfh, g_xfl, g_wvh, mBase, nBase, smem, acc);

    const int tid = threadIdx.x;
    const int lane = tid & 31, wid = tid >> 5;
    const int wm = (wid >> 2) * 64, wn2 = (wid & 3) * 16;

#pragma unroll
    for (int i = 0; i < 4; i++) {
        int gm0 = mBase + wm + i * 16 + (lane >> 2);
#pragma unroll
        for (int rr = 0; rr < 2; rr++) {
            int gm = gm0 + rr * 8;
            int b = gm >> 11, s = gm & (CTXN - 1);
            size_t base = (((size_t)b * NH + head) * CTXN + s) * HD;
#pragma unroll
            for (int jl = 0; jl < 2; jl++) {
                int c = wn2 + jl * 8 + (lane & 3) * 2;
                float lo0 = acc[i][jl][rr * 2 + 0];
                float lo1 = acc[i][jl][rr * 2 + 1];
                float hi0 = acc[i][jl + 2][rr * 2 + 0];
                float hi1 = acc[i][jl + 2][rr * 2 + 1];
                __half a0 = __float2half(lo0), a1 = __float2half(lo1);
                __half b0 = __float2half(hi0), b1 = __float2half(hi1);
                *(__half2*)&g_Vh[base + c]      = __halves2half2(a0, a1);
                *(__half2*)&g_Vh[base + c + 64] = __halves2half2(b0, b1);
                *(__half2*)&g_Vl[base + c]      = __halves2half2(
                    __float2half(lo0 - __half2float(a0)),
                    __float2half(lo1 - __half2float(a1)));
                *(__half2*)&g_Vl[base + c + 64] = __halves2half2(
                    __float2half(hi0 - __half2float(b0)),
                    __float2half(hi1 - __half2float(b1)));
            }
        }
    }
}

// ======================= output projection (fp16 2-term) ===================
__global__ void __launch_bounds__(256, 2) out_tc(float* __restrict__ out) {
    extern __shared__ char smem[];
    const int mBase = blockIdx.y * 128, nBase = blockIdx.x * 128;

    float acc[4][4][4];
    gemm_mainloop_h(g_ctxh, g_ctxl, g_woh, mBase, nBase, smem, acc);

    const int tid = threadIdx.x;
    const int lane = tid & 31, wid = tid >> 5;
    const int wm = (wid >> 2) * 64, wn2 = (wid & 3) * 16;

#pragma unroll
    for (int i = 0; i < 4; i++) {
        int gm0 = mBase + wm + i * 16 + (lane >> 2);
#pragma unroll
        for (int rr = 0; rr < 2; rr++) {
            int gm = gm0 + rr * 8;
            size_t rb = (size_t)gm * DMODEL + nBase;
#pragma unroll
            for (int jl = 0; jl < 2; jl++) {
                int c = wn2 + jl * 8 + (lane & 3) * 2;
                *(float2*)&out[rb + c] =
                    make_float2(acc[i][jl][rr * 2], acc[i][jl][rr * 2 + 1]);
                *(float2*)&out[rb + c + 64] =
                    make_float2(acc[i][jl + 2][rr * 2], acc[i][jl + 2][rr * 2 + 1]);
            }
        }
    }
}

// ======================= tensor-core flash attention =======================
// Q fragments hoisted into registers (loop-invariant): removes 16 ldsm/tile
// and the per-tile ldsm->mma warm-up ramp.  Arithmetic identical to R11.
#define SA 136
#define AQH 0
#define AQL (128 * SA * 2)
#define ASTAGE0 (2 * 128 * SA * 2)               // 69632
#define ASTG (4 * 64 * SA * 2)                   // 69632 per stage
#define AKH 0
#define AKL (64 * SA * 2)
#define AVH (2 * 64 * SA * 2)
#define AVL (3 * 64 * SA * 2)
#define ATTN2_SMEM (ASTAGE0 + 2 * ASTG)          // 208896

__device__ __forceinline__ void load_kv_tile(uint32_t dst, size_t bhoff,
                                             int kvrow, int tid) {
#pragma unroll
    for (int i = 0; i < 4; i++) {
        int cid = tid + i * 256;
        int row = cid >> 4, u = cid & 15;
        uint32_t off = (uint32_t)(row * (SA * 2) + u * 16);
        size_t g = bhoff + (size_t)(kvrow + row) * HD + u * 8;
        cpa16(dst + AKH + off, &g_Kh[g]);
        cpa16(dst + AKL + off, &g_Kl[g]);
        cpa16(dst + AVH + off, &g_Vh[g]);
        cpa16(dst + AVL + off, &g_Vl[g]);
    }
}

__global__ void __launch_bounds__(256, 1) attn_tc() {
    extern __shared__ char smc[];
    uint32_t su = smem_to_u32(smc);
    const int tid = threadIdx.x, lane = tid & 31, wid = tid >> 5;
    const int qt = 15 - (int)blockIdx.x;
    const int bh = blockIdx.y;
    const int b = bh >> 4, h = bh & 15;
    const size_t bhoff = (size_t)bh * CTXN * HD;
    const int qbase = qt * 128;
    const int wm = wid * 16;
    const int ntiles = 2 * qt + 2;

#pragma unroll
    for (int i = 0; i < 8; i++) {
        int cid = tid + i * 256;
        int row = cid >> 4, u = cid & 15;
        uint32_t off = (uint32_t)(row * (SA * 2) + u * 16);
        size_t g = bhoff + (size_t)(qbase + row) * HD + u * 8;
        cpa16(su + AQH + off, &g_Qh[g]);
        cpa16(su + AQL + off, &g_Ql[g]);
    }
    load_kv_tile(su + ASTAGE0, bhoff, 0, tid);
    CP_COMMIT();

    float oacc[16][4];
#pragma unroll
    for (int i = 0; i < 16; i++)
#pragma unroll
        for (int r = 0; r < 4; r++) oacc[i][r] = 0.f;
    float m0 = -INFINITY, m1 = -INFINITY, l0 = 0.f, l1 = 0.f;

    // ---- prologue wait (covers Q and KV tile 0), hoist Q frags to regs ----
    CP_WAIT(0);
    __syncthreads();
    uint32_t qah[8][4], qal[8][4];
#pragma unroll
    for (int ks = 0; ks < 8; ks++) {
        uint32_t aoff = (uint32_t)(((wm + (lane & 15)) * SA
                         + (lane >> 4) * 8 + ks * 16) * 2);
        ldsm4(qah[ks], su + AQH + aoff);
        ldsm4(qal[ks], su + AQL + aoff);
    }

    for (int j = 0; j < ntiles; j++) {
        int buf = j & 1;
        if (j > 0) {
            CP_WAIT(0);
            __syncthreads();
        }
        if (j + 1 < ntiles) {
            load_kv_tile(su + ASTAGE0 + (uint32_t)(buf ^ 1) * ASTG,
                         bhoff, (j + 1) * 64, tid);
            CP_COMMIT();
        }
        const int kvbase = j * 64;
        if (kvbase <= qbase + wm + 15) {
            uint32_t kbh = su + ASTAGE0 + (uint32_t)buf * ASTG + AKH;
            uint32_t kbl = kbh + (AKL - AKH);
            uint32_t vbh = su + ASTAGE0 + (uint32_t)buf * ASTG + AVH;
            uint32_t vbl = vbh + (AVL - AVH);

            float sacc[8][4];
#pragma unroll
            for (int i = 0; i < 8; i++)
#pragma unroll
                for (int r = 0; r < 4; r++) sacc[i][r] = 0.f;
#pragma unroll
            for (int ks = 0; ks < 8; ks++) {
#pragma unroll
                for (int jp = 0; jp < 4; jp++) {
                    int bn = jp * 16 + (lane & 7) + ((lane >> 4) & 1) * 8;
                    int bk = ((lane >> 3) & 1) * 8 + ks * 16;
                    uint32_t boff = (uint32_t)((bn * SA + bk) * 2);
                    uint32_t kh4[4], kl4[4];
                    ldsm4(kh4, kbh + boff);
                    ldsm4(kl4, kbl + boff);
                    mma_bf16(sacc[jp * 2],     qah[ks], &kh4[0]);
                    mma_bf16(sacc[jp * 2 + 1], qah[ks], &kh4[2]);
                    mma_bf16(sacc[jp * 2],     qah[ks], &kl4[0]);
                    mma_bf16(sacc[jp * 2 + 1], qah[ks], &kl4[2]);
                    mma_bf16(sacc[jp * 2],     qal[ks], &kh4[0]);
                    mma_bf16(sacc[jp * 2 + 1], qal[ks], &kh4[2]);
                }
            }

            if (kvbase + 63 > qbase + wm) {
                int row0 = qbase + wm + (lane >> 2);
                int c0 = kvbase + (lane & 3) * 2;
#pragma unroll
                for (int nb = 0; nb < 8; nb++) {
                    int c = c0 + nb * 8;
                    if (c     > row0)     sacc[nb][0] = -1e30f;
                    if (c + 1 > row0)     sacc[nb][1] = -1e30f;
                    if (c     > row0 + 8) sacc[nb][2] = -1e30f;
                    if (c + 1 > row0 + 8) sacc[nb][3] = -1e30f;
                }
            }

            float mx0 = -INFINITY, mx1 = -INFINITY;
#pragma unroll
            for (int nb = 0; nb < 8; nb++) {
                mx0 = fmaxf(mx0, fmaxf(sacc[nb][0], sacc[nb][1]));
                mx1 = fmaxf(mx1, fmaxf(sacc[nb][2], sacc[nb][3]));
            }
            mx0 = fmaxf(mx0, __shfl_xor_sync(0xffffffffu, mx0, 1));
            mx0 = fmaxf(mx0, __shfl_xor_sync(0xffffffffu, mx0, 2));
            mx1 = fmaxf(mx1, __shfl_xor_sync(0xffffffffu, mx1, 1));
            mx1 = fmaxf(mx1, __shfl_xor_sync(0xffffffffu, mx1, 2));
            float mn0 = fmaxf(m0, mx0), mn1 = fmaxf(m1, mx1);
            float a0 = __expf(m0 - mn0), a1 = __expf(m1 - mn1);
            m0 = mn0; m1 = mn1;
            float s0 = 0.f, s1 = 0.f;
#pragma unroll
            for (int nb = 0; nb < 8; nb++) {
                float p0 = __expf(sacc[nb][0] - mn0);
                float p1 = __expf(sacc[nb][1] - mn0);
                float p2 = __expf(sacc[nb][2] - mn1);
                float p3 = __expf(sacc[nb][3] - mn1);
                sacc[nb][0] = p0; sacc[nb][1] = p1;
                sacc[nb][2] = p2; sacc[nb][3] = p3;
                s0 += p0 + p1; s1 += p2 + p3;
            }
            s0 += __shfl_xor_sync(0xffffffffu, s0, 1);
            s0 += __shfl_xor_sync(0xffffffffu, s0, 2);
            s1 += __shfl_xor_sync(0xffffffffu, s1, 1);
            s1 += __shfl_xor_sync(0xffffffffu, s1, 2);
            l0 = l0 * a0 + s0;
            l1 = l1 * a1 + s1;
#pragma unroll
            for (int i = 0; i < 16; i++) {
                oacc[i][0] *= a0; oacc[i][1] *= a0;
                oacc[i][2] *= a1; oacc[i][3] *= a1;
            }

#pragma unroll
            for (int kb = 0; kb < 4; kb++) {
                uint32_t ph[4];
                ph[0] = pack_h16(sacc[2 * kb][0],     sacc[2 * kb][1]);
                ph[1] = pack_h16(sacc[2 * kb][2],     sacc[2 * kb][3]);
                ph[2] = pack_h16(sacc[2 * kb + 1][0], sacc[2 * kb + 1][1]);
                ph[3] = pack_h16(sacc[2 * kb + 1][2], sacc[2 * kb + 1][3]);
#pragma unroll
                for (int jn = 0; jn < 8; jn++) {
                    uint32_t voff = (uint32_t)(((kb * 16 + (lane & 15)) * SA
                                     + jn * 16 + (lane >> 4) * 8) * 2);
                    uint32_t vh4[4], vl4[4];
                    ldsm4t(vh4, vbh + voff);
                    ldsm4t(vl4, vbl + voff);
                    mma_f16(oacc[jn * 2],     ph, &vh4[0]);
                    mma_f16(oacc[jn * 2 + 1], ph, &vh4[2]);
                    mma_f16(oacc[jn * 2],     ph, &vl4[0]);
                    mma_f16(oacc[jn * 2 + 1], ph, &vl4[2]);
                }
            }
        }
    }

    float inv0 = 1.0f / l0, inv1 = 1.0f / l1;
    int sr0 = qbase + wm + (lane >> 2);
    size_t r0i = ((size_t)(b * CTXN + sr0)) * DMODEL + h * HD;
    size_t r1i = r0i + (size_t)8 * DMODEL;
#pragma unroll
    for (int jn = 0; jn < 16; jn++) {
        int c = jn * 8 + (lane & 3) * 2;
        float v0 = oacc[jn][0] * inv0, v1 = oacc[jn][1] * inv0;
        float v2 = oacc[jn][2] * inv1, v3 = oacc[jn][3] * inv1;
        __half h0a = __float2half(v0), h0b = __float2half(v1);
        __half h1a = __float2half(v2), h1b = __float2half(v3);
        *(__half2*)&g_ctxh[r0i + c] = __halves2half2(h0a, h0b);
        *(__half2*)&g_ctxh[r1i + c] = __halves2half2(h1a, h1b);
        *(__half2*)&g_ctxl[r0i + c] = __halves2half2(
            __float2half(v0 - __half2float(h0a)),
            __float2half(v1 - __half2float(h0b)));
        *(__half2*)&g_ctxl[r1i + c] = __halves2half2(
            __float2half(v2 - __half2float(h1a)),
            __float2half(v3 - __half2float(h1b)));
    }
}

// ======================= launch ============================================
extern "C" void kernel_launch(void* const* d_in, const int* in_sizes, int n_in,
                              void* d_out, int out_size)
{
    (void)in_sizes; (void)n_in; (void)out_size;
    const float* x  = (const float*)d_in[0];
    const float* Wq = (const float*)d_in[1];
    const float* Wk = (const float*)d_in[2];
    const float* Wv = (const float*)d_in[3];
    const float* Wo = (const float*)d_in[4];
    float* out = (float*)d_out;

    cudaFuncSetAttribute(qk_tc,   cudaFuncAttributeMaxDynamicSharedMemorySize, GEMM_SMEM);
    cudaFuncSetAttribute(v_tc,    cudaFuncAttributeMaxDynamicSharedMemorySize, GEMM_H_SMEM);
    cudaFuncSetAttribute(out_tc,  cudaFuncAttributeMaxDynamicSharedMemorySize, GEMM_H_SMEM);
    cudaFuncSetAttribute(attn_tc, cudaFuncAttributeMaxDynamicSharedMemorySize, ATTN2_SMEM);

    conv_x<<<(MROWS * DMODEL / 4) / 256, 256>>>(x);
    conv_w<<<dim3(64, 64, 4), dim3(32, 8)>>>(Wq, Wk, Wv, Wo);
    rope_table<<<64, 256>>>();
    qk_tc<<<dim3(DMODEL / 128, MROWS / 128, 2), 256, GEMM_SMEM>>>();
    v_tc<<<dim3(DMODEL / 128, MROWS / 128), 256, GEMM_H_SMEM>>>();
    attn_tc<<<dim3(16, 32), 256, ATTN2_SMEM>>>();
    out_tc<<<dim3(DMODEL / 128, MROWS / 128), 256, GEMM_H_SMEM>>>(out);
}

// round 17
// speedup vs baseline: 1.1031x; 1.0150x over previous
#include <cuda_runtime.h>
#include <cuda_bf16.h>
#include <cuda_fp16.h>
#include <cstdint>
#include <math.h>

#define CTXN   2048
#define DMODEL 2048
#define NH     16
#define HD     128
#define BSZ    2
#define MROWS  (BSZ * CTXN)   // 4096

// ---------------- scratch (device globals; no allocation allowed) ----------
__device__ __nv_bfloat16 g_xh[MROWS * DMODEL];     // x bf16 hi/lo (QK proj)
__device__ __nv_bfloat16 g_xl[MROWS * DMODEL];
__device__ __half        g_xfh[MROWS * DMODEL];    // x fp16 hi/lo (V proj)
__device__ __half        g_xfl[MROWS * DMODEL];
__device__ __nv_bfloat16 g_wqh[DMODEL * DMODEL], g_wql[DMODEL * DMODEL];
__device__ __nv_bfloat16 g_wkh[DMODEL * DMODEL], g_wkl[DMODEL * DMODEL];
__device__ __half        g_wvh[DMODEL * DMODEL];   // Wv fp16 single
__device__ __half        g_woh[DMODEL * DMODEL];   // Wo fp16 single
__device__ __nv_bfloat16 g_Qh[BSZ * NH * CTXN * HD], g_Ql[BSZ * NH * CTXN * HD];
__device__ __nv_bfloat16 g_Kh[BSZ * NH * CTXN * HD], g_Kl[BSZ * NH * CTXN * HD];
__device__ __half        g_Vh[BSZ * NH * CTXN * HD], g_Vl[BSZ * NH * CTXN * HD];
__device__ __half        g_ctxh[MROWS * DMODEL];   // ctx fp16 hi/lo
__device__ __half        g_ctxl[MROWS * DMODEL];
__device__ float2 g_rope[64 * CTXN];               // [d][s] (sin, cos)

// ======================= low-level helpers =================================
__device__ __forceinline__ uint32_t smem_to_u32(const void* p) {
    uint32_t a;
    asm("{ .reg .u64 t; cvta.to.shared.u64 t, %1; cvt.u32.u64 %0, t; }"
        : "=r"(a) : "l"(p));
    return a;
}
__device__ __forceinline__ void cpa16(uint32_t dst, const void* src) {
    asm volatile("cp.async.cg.shared.global [%0], [%1], 16;" :: "r"(dst), "l"(src));
}
#define CP_COMMIT() asm volatile("cp.async.commit_group;" ::: "memory")
#define CP_WAIT(n)  asm volatile("cp.async.wait_group %0;" :: "n"(n) : "memory")

__device__ __forceinline__ void ldsm4(uint32_t* r, uint32_t addr) {
    asm volatile("ldmatrix.sync.aligned.m8n8.x4.shared.b16 {%0,%1,%2,%3}, [%4];"
        : "=r"(r[0]), "=r"(r[1]), "=r"(r[2]), "=r"(r[3]) : "r"(addr));
}
__device__ __forceinline__ void ldsm4t(uint32_t* r, uint32_t addr) {
    asm volatile("ldmatrix.sync.aligned.m8n8.x4.trans.shared.b16 {%0,%1,%2,%3}, [%4];"
        : "=r"(r[0]), "=r"(r[1]), "=r"(r[2]), "=r"(r[3]) : "r"(addr));
}
__device__ __forceinline__ void mma_bf16(float* d, const uint32_t* a, const uint32_t* b) {
    asm volatile(
        "mma.sync.aligned.m16n8k16.row.col.f32.bf16.bf16.f32 "
        "{%0,%1,%2,%3}, {%4,%5,%6,%7}, {%8,%9}, {%0,%1,%2,%3};"
        : "+f"(d[0]), "+f"(d[1]), "+f"(d[2]), "+f"(d[3])
        : "r"(a[0]), "r"(a[1]), "r"(a[2]), "r"(a[3]), "r"(b[0]), "r"(b[1]));
}
__device__ __forceinline__ void mma_f16(float* d, const uint32_t* a, const uint32_t* b) {
    asm volatile(
        "mma.sync.aligned.m16n8k16.row.col.f32.f16.f16.f32 "
        "{%0,%1,%2,%3}, {%4,%5,%6,%7}, {%8,%9}, {%0,%1,%2,%3};"
        : "+f"(d[0]), "+f"(d[1]), "+f"(d[2]), "+f"(d[3])
        : "r"(a[0]), "r"(a[1]), "r"(a[2]), "r"(a[3]), "r"(b[0]), "r"(b[1]));
}
__device__ __forceinline__ uint32_t pack_h16(float a, float b) {
    __half2 p = __halves2half2(__float2half(a), __float2half(b));
    return *(uint32_t*)&p;
}

// ======================= prep kernels ======================================
__global__ void conv_x(const float* __restrict__ x) {
    size_t i = (size_t)blockIdx.x * 256 + threadIdx.x;   // over elems/4
    float4 v = ((const float4*)x)[i];
    float vv[4] = {v.x, v.y, v.z, v.w};
#pragma unroll
    for (int p = 0; p < 2; p++) {
        float a = vv[2 * p], b = vv[2 * p + 1];
        __nv_bfloat16 bh0 = __float2bfloat16(a), bh1 = __float2bfloat16(b);
        ((__nv_bfloat162*)g_xh)[2 * i + p] = __halves2bfloat162(bh0, bh1);
        ((__nv_bfloat162*)g_xl)[2 * i + p] = __halves2bfloat162(
            __float2bfloat16(a - __bfloat162float(bh0)),
            __float2bfloat16(b - __bfloat162float(bh1)));
        __half fh0 = __float2half(a), fh1 = __float2half(b);
        ((__half2*)g_xfh)[2 * i + p] = __halves2half2(fh0, fh1);
        ((__half2*)g_xfl)[2 * i + p] = __halves2half2(
            __float2half(a - __half2float(fh0)),
            __float2half(b - __half2float(fh1)));
    }
}

// transpose + convert: out[n][k] = W[k][n].  z 0/1: bf16 hi/lo; z 2/3: fp16 single.
__global__ void conv_w(const float* __restrict__ Wq, const float* __restrict__ Wk,
                       const float* __restrict__ Wv, const float* __restrict__ Wo) {
    __shared__ float t[32][33];
    int z = blockIdx.z;
    const float* W = (z == 0) ? Wq : (z == 1) ? Wk : (z == 2) ? Wv : Wo;
    int bx = blockIdx.x * 32, by = blockIdx.y * 32;     // bx: n, by: k
    int tx = threadIdx.x, ty = threadIdx.y;
#pragma unroll
    for (int i = 0; i < 4; i++)
        t[ty + i * 8][tx] = W[(size_t)(by + ty + i * 8) * DMODEL + bx + tx];
    __syncthreads();
#pragma unroll
    for (int i = 0; i < 4; i++) {
        float v = t[tx][ty + i * 8];
        size_t oi = (size_t)(bx + ty + i * 8) * DMODEL + by + tx;
        if (z < 2) {
            __nv_bfloat16 h = __float2bfloat16(v);
            __nv_bfloat16 l = __float2bfloat16(v - __bfloat162float(h));
            if (z == 0) { g_wqh[oi] = h; g_wql[oi] = l; }
            else        { g_wkh[oi] = h; g_wkl[oi] = l; }
        } else {
            __half h = __float2half(v);
            if (z == 2) g_wvh[oi] = h;
            else        g_woh[oi] = h;
        }
    }
}

__global__ void rope_table() {
    int d = blockIdx.x;                                  // 0..63
    double invf = pow(10000.0, -(double)d / 64.0);
    const double TWO_PI = 6.283185307179586476925286766559;
    for (int s = threadIdx.x; s < CTXN; s += blockDim.x) {
        double a = (double)s * invf;
        double r = a - TWO_PI * floor(a / TWO_PI);
        float sn, cs;
        sincosf((float)r, &sn, &cs);
        g_rope[d * CTXN + s] = make_float2(sn, cs);
    }
}

// ======================= bf16 3-term GEMM core (unchanged, 2m x 4n) ========
#define KC 32
#define SROW 40
#define MAT_BYTES (128 * SROW * 2)            // 10240
#define STAGE_BYTES (4 * MAT_BYTES)           // 40960
#define GEMM_SMEM (2 * STAGE_BYTES)           // 81920
#define NCHUNK (DMODEL / KC)                  // 64

__device__ __forceinline__ void load_stage(
    uint32_t sb, int kt,
    const __nv_bfloat16* __restrict__ Ah, const __nv_bfloat16* __restrict__ Al,
    const __nv_bfloat16* __restrict__ Bh, const __nv_bfloat16* __restrict__ Bl,
    int mBase, int nBase, int tid)
{
#pragma unroll
    for (int i = 0; i < 2; i++) {
        int fid = tid + i * 256;
        int row = fid >> 2, u = fid & 3;
        uint32_t off = (uint32_t)(row * (SROW * 2) + u * 16);
        size_t ga = (size_t)(mBase + row) * DMODEL + kt + u * 8;
        size_t gb = (size_t)(nBase + row) * DMODEL + kt + u * 8;
        cpa16(sb + off,                 &Ah[ga]);
        cpa16(sb + MAT_BYTES + off,     &Al[ga]);
        cpa16(sb + 2 * MAT_BYTES + off, &Bh[gb]);
        cpa16(sb + 3 * MAT_BYTES + off, &Bl[gb]);
    }
}

__device__ __forceinline__ void compute_stage(
    uint32_t sb, int wm, int wn2, int lane, float (&acc)[4][4][4])
{
    uint32_t Ab  = sb;
    uint32_t Alb = sb + MAT_BYTES;
    uint32_t Bb  = sb + 2 * MAT_BYTES;
    uint32_t Blb = sb + 3 * MAT_BYTES;
#pragma unroll
    for (int ks = 0; ks < KC / 16; ks++) {
        uint32_t ah[4][4], al[4][4];
#pragma unroll
        for (int i = 0; i < 4; i++) {
            uint32_t aoff = (uint32_t)(((wm + i * 16 + (lane & 15)) * SROW
                             + (lane >> 4) * 8 + ks * 16) * 2);
            ldsm4(ah[i], Ab + aoff);
            ldsm4(al[i], Alb + aoff);
        }
        uint32_t bh[2][4], bl[2][4];
#pragma unroll
        for (int jp = 0; jp < 2; jp++) {
            int bn = wn2 + jp * 64 + (lane & 7) + ((lane >> 4) & 1) * 8;
            int bk = ((lane >> 3) & 1) * 8 + ks * 16;
            uint32_t boff = (uint32_t)((bn * SROW + bk) * 2);
            ldsm4(bh[jp], Bb + boff);
            ldsm4(bl[jp], Blb + boff);
        }
#pragma unroll
        for (int i = 0; i < 4; i++) {
#pragma unroll
            for (int jp = 0; jp < 2; jp++) {
                mma_bf16(acc[i][jp * 2],     ah[i], &bh[jp][0]);
                mma_bf16(acc[i][jp * 2 + 1], ah[i], &bh[jp][2]);
                mma_bf16(acc[i][jp * 2],     ah[i], &bl[jp][0]);
                mma_bf16(acc[i][jp * 2 + 1], ah[i], &bl[jp][2]);
                mma_bf16(acc[i][jp * 2],     al[i], &bh[jp][0]);
                mma_bf16(acc[i][jp * 2 + 1], al[i], &bh[jp][2]);
            }
        }
    }
}

__device__ __forceinline__ void gemm_mainloop(
    const __nv_bfloat16* __restrict__ Ah, const __nv_bfloat16* __restrict__ Al,
    const __nv_bfloat16* __restrict__ Bh, const __nv_bfloat16* __restrict__ Bl,
    int mBase, int nBase, char* smem, float (&acc)[4][4][4])
{
    uint32_t smem_u = smem_to_u32(smem);
    const int tid = threadIdx.x;
    const int lane = tid & 31, wid = tid >> 5;
    const int wm = (wid >> 2) * 64, wn2 = (wid & 3) * 16;

#pragma unroll
    for (int i = 0; i < 4; i++)
#pragma unroll
        for (int j = 0; j < 4; j++)
#pragma unroll
            for (int r = 0; r < 4; r++) acc[i][j][r] = 0.f;

    load_stage(smem_u, 0, Ah, Al, Bh, Bl, mBase, nBase, tid);
    CP_COMMIT();

    for (int c = 0; c < NCHUNK; c++) {
        CP_WAIT(0);
        __syncthreads();
        if (c + 1 < NCHUNK) {
            load_stage(smem_u + (uint32_t)((c + 1) & 1) * STAGE_BYTES,
                       (c + 1) * KC, Ah, Al, Bh, Bl, mBase, nBase, tid);
            CP_COMMIT();
        }
        compute_stage(smem_u + (uint32_t)(c & 1) * STAGE_BYTES, wm, wn2, lane, acc);
    }
}

// ======================= fp16 2-term GEMM core (4m x 2n warp grid) =========
// Warp tile 32m x 64n: hi/lo A redundancy 4->2, single B 2->4.
// ldsm per chunk 160 -> 128 (-20% crossbar).  Same mma set & order.
#define STAGE_H (3 * MAT_BYTES)               // 30720
#define GEMM_H_SMEM (2 * STAGE_H)             // 61440

__device__ __forceinline__ void load_stage_h(
    uint32_t sb, int kt,
    const __half* __restrict__ Ah, const __half* __restrict__ Al,
    const __half* __restrict__ Bh,
    int mBase, int nBase, int tid)
{
#pragma unroll
    for (int i = 0; i < 2; i++) {
        int fid = tid + i * 256;
        int row = fid >> 2, u = fid & 3;
        uint32_t off = (uint32_t)(row * (SROW * 2) + u * 16);
        size_t ga = (size_t)(mBase + row) * DMODEL + kt + u * 8;
        size_t gb = (size_t)(nBase + row) * DMODEL + kt + u * 8;
        cpa16(sb + off,                 &Ah[ga]);
        cpa16(sb + MAT_BYTES + off,     &Al[ga]);
        cpa16(sb + 2 * MAT_BYTES + off, &Bh[gb]);
    }
}

__device__ __forceinline__ void compute_stage_h(
    uint32_t sb, int wm, int wn, int lane, float (&acc)[2][8][4])
{
    uint32_t Ab  = sb;
    uint32_t Alb = sb + MAT_BYTES;
    uint32_t Bb  = sb + 2 * MAT_BYTES;
#pragma unroll
    for (int ks = 0; ks < KC / 16; ks++) {
        uint32_t ah[2][4], al[2][4];
#pragma unroll
        for (int i = 0; i < 2; i++) {
            uint32_t aoff = (uint32_t)(((wm + i * 16 + (lane & 15)) * SROW
                             + (lane >> 4) * 8 + ks * 16) * 2);
            ldsm4(ah[i], Ab + aoff);
            ldsm4(al[i], Alb + aoff);
        }
        uint32_t bh[4][4];
#pragma unroll
        for (int jp = 0; jp < 4; jp++) {
            int bn = wn + jp * 16 + (lane & 7) + ((lane >> 4) & 1) * 8;
            int bk = ((lane >> 3) & 1) * 8 + ks * 16;
            uint32_t boff = (uint32_t)((bn * SROW + bk) * 2);
            ldsm4(bh[jp], Bb + boff);
        }
#pragma unroll
        for (int i = 0; i < 2; i++) {
#pragma unroll
            for (int jp = 0; jp < 4; jp++) {
                mma_f16(acc[i][jp * 2],     ah[i], &bh[jp][0]);
                mma_f16(acc[i][jp * 2 + 1], ah[i], &bh[jp][2]);
                mma_f16(acc[i][jp * 2],     al[i], &bh[jp][0]);
                mma_f16(acc[i][jp * 2 + 1], al[i], &bh[jp][2]);
            }
        }
    }
}

__device__ __forceinline__ void gemm_mainloop_h(
    const __half* __restrict__ Ah, const __half* __restrict__ Al,
    const __half* __restrict__ Bh,
    int mBase, int nBase, char* smem, float (&acc)[2][8][4])
{
    uint32_t smem_u = smem_to_u32(smem);
    const int tid = threadIdx.x;
    const int lane = tid & 31, wid = tid >> 5;
    const int wm = (wid & 3) * 32, wn = (wid >> 2) * 64;

#pragma unroll
    for (int i = 0; i < 2; i++)
#pragma unroll
        for (int j = 0; j < 8; j++)
#pragma unroll
            for (int r = 0; r < 4; r++) acc[i][j][r] = 0.f;

    load_stage_h(smem_u, 0, Ah, Al, Bh, mBase, nBase, tid);
    CP_COMMIT();

    for (int c = 0; c < NCHUNK; c++) {
        CP_WAIT(0);
        __syncthreads();
        if (c + 1 < NCHUNK) {
            load_stage_h(smem_u + (uint32_t)((c + 1) & 1) * STAGE_H,
                         (c + 1) * KC, Ah, Al, Bh, mBase, nBase, tid);
            CP_COMMIT();
        }
        compute_stage_h(smem_u + (uint32_t)(c & 1) * STAGE_H, wm, wn, lane, acc);
    }
}

// ======================= QK GEMM (+ fused RoPE, bf16 hi/lo out) ============
__global__ void __launch_bounds__(256, 2) qk_tc() {
    extern __shared__ char smem[];
    const int z = blockIdx.z;                    // 0=Q, 1=K
    const __nv_bfloat16* Bh_ = (z == 0) ? g_wqh : g_wkh;
    const __nv_bfloat16* Bl_ = (z == 0) ? g_wql : g_wkl;
    __nv_bfloat16* Dh = (z == 0) ? g_Qh : g_Kh;
    __nv_bfloat16* Dl = (z == 0) ? g_Ql : g_Kl;
    const int mBase = blockIdx.y * 128, nBase = blockIdx.x * 128;
    const int head = blockIdx.x;

    float acc[4][4][4];
    gemm_mainloop(g_xh, g_xl, Bh_, Bl_, mBase, nBase, smem, acc);

    const int tid = threadIdx.x;
    const int lane = tid & 31, wid = tid >> 5;
    const int wm = (wid >> 2) * 64, wn2 = (wid & 3) * 16;

#pragma unroll
    for (int i = 0; i < 4; i++) {
        int gm0 = mBase + wm + i * 16 + (lane >> 2);
#pragma unroll
        for (int rr = 0; rr < 2; rr++) {
            int gm = gm0 + rr * 8;
            int b = gm >> 11, s = gm & (CTXN - 1);
            size_t base = (((size_t)b * NH + head) * CTXN + s) * HD;
#pragma unroll
            for (int jl = 0; jl < 2; jl++) {
                int c = wn2 + jl * 8 + (lane & 3) * 2;
                float lo0 = acc[i][jl][rr * 2 + 0];
                float lo1 = acc[i][jl][rr * 2 + 1];
                float hi0 = acc[i][jl + 2][rr * 2 + 0];
                float hi1 = acc[i][jl + 2][rr * 2 + 1];
                float2 sc0 = g_rope[c * CTXN + s];
                float2 sc1 = g_rope[(c + 1) * CTXN + s];
                float t0 = lo0 * sc0.y - hi0 * sc0.x;
                float t2 = hi0 * sc0.y + lo0 * sc0.x;
                float t1 = lo1 * sc1.y - hi1 * sc1.x;
                float t3 = hi1 * sc1.y + lo1 * sc1.x;
                lo0 = t0; lo1 = t1; hi0 = t2; hi1 = t3;
                __nv_bfloat16 a0 = __float2bfloat16(lo0), a1 = __float2bfloat16(lo1);
                __nv_bfloat16 b0 = __float2bfloat16(hi0), b1 = __float2bfloat16(hi1);
                *(__nv_bfloat162*)&Dh[base + c]      = __halves2bfloat162(a0, a1);
                *(__nv_bfloat162*)&Dh[base + c + 64] = __halves2bfloat162(b0, b1);
                *(__nv_bfloat162*)&Dl[base + c]      = __halves2bfloat162(
                    __float2bfloat16(lo0 - __bfloat162float(a0)),
                    __float2bfloat16(lo1 - __bfloat162float(a1)));
                *(__nv_bfloat162*)&Dl[base + c + 64] = __halves2bfloat162(
                    __float2bfloat16(hi0 - __bfloat162float(b0)),
                    __float2bfloat16(hi1 - __bfloat162float(b1)));
            }
        }
    }
}

// ======================= V GEMM (fp16 2-term, 4m x 2n) =====================
__global__ void __launch_bounds__(256, 2) v_tc() {
    extern __shared__ char smem[];
    const int mBase = blockIdx.y * 128, nBase = blockIdx.x * 128;
    const int head = blockIdx.x;

    float acc[2][8][4];
    gemm_mainloop_h(g_xfh, g_xfl, g_wvh, mBase, nBase, smem, acc);

    const int tid = threadIdx.x;
    const int lane = tid & 31, wid = tid >> 5;
    const int wm = (wid & 3) * 32, wn = (wid >> 2) * 64;

#pragma unroll
    for (int i = 0; i < 2; i++) {
        int gm0 = mBase + wm + i * 16 + (lane >> 2);
#pragma unroll
        for (int rr = 0; rr < 2; rr++) {
            int gm = gm0 + rr * 8;
            int b = gm >> 11, s = gm & (CTXN - 1);
            size_t base = (((size_t)b * NH + head) * CTXN + s) * HD;
#pragma unroll
            for (int jf = 0; jf < 8; jf++) {
                int c = wn + jf * 8 + (lane & 3) * 2;
                float v0 = acc[i][jf][rr * 2 + 0];
                float v1 = acc[i][jf][rr * 2 + 1];
                __half a0 = __float2half(v0), a1 = __float2half(v1);
                *(__half2*)&g_Vh[base + c] = __halves2half2(a0, a1);
                *(__half2*)&g_Vl[base + c] = __halves2half2(
                    __float2half(v0 - __half2float(a0)),
                    __float2half(v1 - __half2float(a1)));
            }
        }
    }
}

// ======================= output projection (fp16 2-term, 4m x 2n) ==========
__global__ void __launch_bounds__(256, 2) out_tc(float* __restrict__ out) {
    extern __shared__ char smem[];
    const int mBase = blockIdx.y * 128, nBase = blockIdx.x * 128;

    float acc[2][8][4];
    gemm_mainloop_h(g_ctxh, g_ctxl, g_woh, mBase, nBase, smem, acc);

    const int tid = threadIdx.x;
    const int lane = tid & 31, wid = tid >> 5;
    const int wm = (wid & 3) * 32, wn = (wid >> 2) * 64;

#pragma unroll
    for (int i = 0; i < 2; i++) {
        int gm0 = mBase + wm + i * 16 + (lane >> 2);
#pragma unroll
        for (int rr = 0; rr < 2; rr++) {
            int gm = gm0 + rr * 8;
            size_t rb = (size_t)gm * DMODEL + nBase;
#pragma unroll
            for (int jf = 0; jf < 8; jf++) {
                int c = wn + jf * 8 + (lane & 3) * 2;
                *(float2*)&out[rb + c] =
                    make_float2(acc[i][jf][rr * 2], acc[i][jf][rr * 2 + 1]);
            }
        }
    }
}

// ======================= tensor-core flash attention =======================
#define SA 136
#define AQH 0
#define AQL (128 * SA * 2)
#define ASTAGE0 (2 * 128 * SA * 2)               // 69632
#define ASTG (4 * 64 * SA * 2)                   // 69632 per stage
#define AKH 0
#define AKL (64 * SA * 2)
#define AVH (2 * 64 * SA * 2)
#define AVL (3 * 64 * SA * 2)
#define ATTN2_SMEM (ASTAGE0 + 2 * ASTG)          // 208896

__device__ __forceinline__ void load_kv_tile(uint32_t dst, size_t bhoff,
                                             int kvrow, int tid) {
#pragma unroll
    for (int i = 0; i < 4; i++) {
        int cid = tid + i * 256;
        int row = cid >> 4, u = cid & 15;
        uint32_t off = (uint32_t)(row * (SA * 2) + u * 16);
        size_t g = bhoff + (size_t)(kvrow + row) * HD + u * 8;
        cpa16(dst + AKH + off, &g_Kh[g]);
        cpa16(dst + AKL + off, &g_Kl[g]);
        cpa16(dst + AVH + off, &g_Vh[g]);
        cpa16(dst + AVL + off, &g_Vl[g]);
    }
}

__global__ void __launch_bounds__(256, 1) attn_tc() {
    extern __shared__ char smc[];
    uint32_t su = smem_to_u32(smc);
    const int tid = threadIdx.x, lane = tid & 31, wid = tid >> 5;
    const int qt = 15 - (int)blockIdx.x;
    const int bh = blockIdx.y;
    const int b = bh >> 4, h = bh & 15;
    const size_t bhoff = (size_t)bh * CTXN * HD;
    const int qbase = qt * 128;
    const int wm = wid * 16;
    const int ntiles = 2 * qt + 2;

#pragma unroll
    for (int i = 0; i < 8; i++) {
        int cid = tid + i * 256;
        int row = cid >> 4, u = cid & 15;
        uint32_t off = (uint32_t)(row * (SA * 2) + u * 16);
        size_t g = bhoff + (size_t)(qbase + row) * HD + u * 8;
        cpa16(su + AQH + off, &g_Qh[g]);
        cpa16(su + AQL + off, &g_Ql[g]);
    }
    load_kv_tile(su + ASTAGE0, bhoff, 0, tid);
    CP_COMMIT();

    float oacc[16][4];
#pragma unroll
    for (int i = 0; i < 16; i++)
#pragma unroll
        for (int r = 0; r < 4; r++) oacc[i][r] = 0.f;
    float m0 = -INFINITY, m1 = -INFINITY, l0 = 0.f, l1 = 0.f;

    // ---- prologue wait (covers Q and KV tile 0), hoist Q frags to regs ----
    CP_WAIT(0);
    __syncthreads();
    uint32_t qah[8][4], qal[8][4];
#pragma unroll
    for (int ks = 0; ks < 8; ks++) {
        uint32_t aoff = (uint32_t)(((wm + (lane & 15)) * SA
                         + (lane >> 4) * 8 + ks * 16) * 2);
        ldsm4(qah[ks], su + AQH + aoff);
        ldsm4(qal[ks], su + AQL + aoff);
    }

    for (int j = 0; j < ntiles; j++) {
        int buf = j & 1;
        if (j > 0) {
            CP_WAIT(0);
            __syncthreads();
        }
        if (j + 1 < ntiles) {
            load_kv_tile(su + ASTAGE0 + (uint32_t)(buf ^ 1) * ASTG,
                         bhoff, (j + 1) * 64, tid);
            CP_COMMIT();
        }
        const int kvbase = j * 64;
        if (kvbase <= qbase + wm + 15) {
            uint32_t kbh = su + ASTAGE0 + (uint32_t)buf * ASTG + AKH;
            uint32_t kbl = kbh + (AKL - AKH);
            uint32_t vbh = su + ASTAGE0 + (uint32_t)buf * ASTG + AVH;
            uint32_t vbl = vbh + (AVL - AVH);

            float sacc[8][4];
#pragma unroll
            for (int i = 0; i < 8; i++)
#pragma unroll
                for (int r = 0; r < 4; r++) sacc[i][r] = 0.f;
#pragma unroll
            for (int ks = 0; ks < 8; ks++) {
#pragma unroll
                for (int jp = 0; jp < 4; jp++) {
                    int bn = jp * 16 + (lane & 7) + ((lane >> 4) & 1) * 8;
                    int bk = ((lane >> 3) & 1) * 8 + ks * 16;
                    uint32_t boff = (uint32_t)((bn * SA + bk) * 2);
                    uint32_t kh4[4], kl4[4];
                    ldsm4(kh4, kbh + boff);
                    ldsm4(kl4, kbl + boff);
                    mma_bf16(sacc[jp * 2],     qah[ks], &kh4[0]);
                    mma_bf16(sacc[jp * 2 + 1], qah[ks], &kh4[2]);
                    mma_bf16(sacc[jp * 2],     qah[ks], &kl4[0]);
                    mma_bf16(sacc[jp * 2 + 1], qah[ks], &kl4[2]);
                    mma_bf16(sacc[jp * 2],     qal[ks], &kh4[0]);
                    mma_bf16(sacc[jp * 2 + 1], qal[ks], &kh4[2]);
                }
            }

            if (kvbase + 63 > qbase + wm) {
                int row0 = qbase + wm + (lane >> 2);
                int c0 = kvbase + (lane & 3) * 2;
#pragma unroll
                for (int nb = 0; nb < 8; nb++) {
                    int c = c0 + nb * 8;
                    if (c     > row0)     sacc[nb][0] = -1e30f;
                    if (c + 1 > row0)     sacc[nb][1] = -1e30f;
                    if (c     > row0 + 8) sacc[nb][2] = -1e30f;
                    if (c + 1 > row0 + 8) sacc[nb][3] = -1e30f;
                }
            }

            float mx0 = -INFINITY, mx1 = -INFINITY;
#pragma unroll
            for (int nb = 0; nb < 8; nb++) {
                mx0 = fmaxf(mx0, fmaxf(sacc[nb][0], sacc[nb][1]));
                mx1 = fmaxf(mx1, fmaxf(sacc[nb][2], sacc[nb][3]));
            }
            mx0 = fmaxf(mx0, __shfl_xor_sync(0xffffffffu, mx0, 1));
            mx0 = fmaxf(mx0, __shfl_xor_sync(0xffffffffu, mx0, 2));
            mx1 = fmaxf(mx1, __shfl_xor_sync(0xffffffffu, mx1, 1));
            mx1 = fmaxf(mx1, __shfl_xor_sync(0xffffffffu, mx1, 2));
            float mn0 = fmaxf(m0, mx0), mn1 = fmaxf(m1, mx1);
            float a0 = __expf(m0 - mn0), a1 = __expf(m1 - mn1);
            m0 = mn0; m1 = mn1;
            float s0 = 0.f, s1 = 0.f;
#pragma unroll
            for (int nb = 0; nb < 8; nb++) {
                float p0 = __expf(sacc[nb][0] - mn0);
                float p1 = __expf(sacc[nb][1] - mn0);
                float p2 = __expf(sacc[nb][2] - mn1);
                float p3 = __expf(sacc[nb][3] - mn1);
                sacc[nb][0] = p0; sacc[nb][1] = p1;
                sacc[nb][2] = p2; sacc[nb][3] = p3;
                s0 += p0 + p1; s1 += p2 + p3;
            }
            s0 += __shfl_xor_sync(0xffffffffu, s0, 1);
            s0 += __shfl_xor_sync(0xffffffffu, s0, 2);
            s1 += __shfl_xor_sync(0xffffffffu, s1, 1);
            s1 += __shfl_xor_sync(0xffffffffu, s1, 2);
            l0 = l0 * a0 + s0;
            l1 = l1 * a1 + s1;
#pragma unroll
            for (int i = 0; i < 16; i++) {
                oacc[i][0] *= a0; oacc[i][1] *= a0;
                oacc[i][2] *= a1; oacc[i][3] *= a1;
            }

#pragma unroll
            for (int kb = 0; kb < 4; kb++) {
                uint32_t ph[4];
                ph[0] = pack_h16(sacc[2 * kb][0],     sacc[2 * kb][1]);
                ph[1] = pack_h16(sacc[2 * kb][2],     sacc[2 * kb][3]);
                ph[2] = pack_h16(sacc[2 * kb + 1][0], sacc[2 * kb + 1][1]);
                ph[3] = pack_h16(sacc[2 * kb + 1][2], sacc[2 * kb + 1][3]);
#pragma unroll
                for (int jn = 0; jn < 8; jn++) {
                    uint32_t voff = (uint32_t)(((kb * 16 + (lane & 15)) * SA
                                     + jn * 16 + (lane >> 4) * 8) * 2);
                    uint32_t vh4[4], vl4[4];
                    ldsm4t(vh4, vbh + voff);
                    ldsm4t(vl4, vbl + voff);
                    mma_f16(oacc[jn * 2],     ph, &vh4[0]);
                    mma_f16(oacc[jn * 2 + 1], ph, &vh4[2]);
                    mma_f16(oacc[jn * 2],     ph, &vl4[0]);
                    mma_f16(oacc[jn * 2 + 1], ph, &vl4[2]);
                }
            }
        }
    }

    float inv0 = 1.0f / l0, inv1 = 1.0f / l1;
    int sr0 = qbase + wm + (lane >> 2);
    size_t r0i = ((size_t)(b * CTXN + sr0)) * DMODEL + h * HD;
    size_t r1i = r0i + (size_t)8 * DMODEL;
#pragma unroll
    for (int jn = 0; jn < 16; jn++) {
        int c = jn * 8 + (lane & 3) * 2;
        float v0 = oacc[jn][0] * inv0, v1 = oacc[jn][1] * inv0;
        float v2 = oacc[jn][2] * inv1, v3 = oacc[jn][3] * inv1;
        __half h0a = __float2half(v0), h0b = __float2half(v1);
        __half h1a = __float2half(v2), h1b = __float2half(v3);
        *(__half2*)&g_ctxh[r0i + c] = __halves2half2(h0a, h0b);
        *(__half2*)&g_ctxh[r1i + c] = __halves2half2(h1a, h1b);
        *(__half2*)&g_ctxl[r0i + c] = __halves2half2(
            __float2half(v0 - __half2float(h0a)),
            __float2half(v1 - __half2float(h0b)));
        *(__half2*)&g_ctxl[r1i + c] = __halves2half2(
            __float2half(v2 - __half2float(h1a)),
            __float2half(v3 - __half2float(h1b)));
    }
}

// ======================= launch ============================================
extern "C" void kernel_launch(void* const* d_in, const int* in_sizes, int n_in,
                              void* d_out, int out_size)
{
    (void)in_sizes; (void)n_in; (void)out_size;
    const float* x  = (const float*)d_in[0];
    const float* Wq = (const float*)d_in[1];
    const float* Wk = (const float*)d_in[2];
    const float* Wv = (const float*)d_in[3];
    const float* Wo = (const float*)d_in[4];
    float* out = (float*)d_out;

    cudaFuncSetAttribute(qk_tc,   cudaFuncAttributeMaxDynamicSharedMemorySize, GEMM_SMEM);
    cudaFuncSetAttribute(v_tc,    cudaFuncAttributeMaxDynamicSharedMemorySize, GEMM_H_SMEM);
    cudaFuncSetAttribute(out_tc,  cudaFuncAttributeMaxDynamicSharedMemorySize, GEMM_H_SMEM);
    cudaFuncSetAttribute(attn_tc, cudaFuncAttributeMaxDynamicSharedMemorySize, ATTN2_SMEM);

    conv_x<<<(MROWS * DMODEL / 4) / 256, 256>>>(x);
    conv_w<<<dim3(64, 64, 4), dim3(32, 8)>>>(Wq, Wk, Wv, Wo);
    rope_table<<<64, 256>>>();
    qk_tc<<<dim3(DMODEL / 128, MROWS / 128, 2), 256, GEMM_SMEM>>>();
    v_tc<<<dim3(DMODEL / 128, MROWS / 128), 256, GEMM_H_SMEM>>>();
    attn_tc<<<dim3(16, 32), 256, ATTN2_SMEM>>>();
    out_tc<<<dim3(DMODEL / 128, MROWS / 128), 256, GEMM_H_SMEM>>>(out);
}